// round 1
// baseline (speedup 1.0000x reference)
#include <cuda_runtime.h>

typedef unsigned long long u64;

// ---------------- scratch (static __device__, no allocations) ----------------
__device__ float g_q[16777216];          // [128][131072] = [r=131072][128] rows
__device__ float g_k[16777216];
__device__ float g_v[16777216];
__device__ float g_spart[256 * 16384];   // split-K partial score tiles
__device__ float g_scores[16384];        // [128][128]
__device__ float g_attnT[16384];         // transposed softmax(attn): [n2][n]
__device__ float g_pe[1024];             // per-s PE scalar

// ---------------- f32x2 packed helpers ----------------
__device__ __forceinline__ u64 ff2_pack(float lo, float hi) {
    u64 r; asm("mov.b64 %0, {%1, %2};" : "=l"(r) : "f"(lo), "f"(hi)); return r;
}
__device__ __forceinline__ void ff2_fma(u64 &d, u64 a, u64 b) {
    asm("fma.rn.f32x2 %0, %1, %2, %0;" : "+l"(d) : "l"(a), "l"(b));
}
__device__ __forceinline__ float ff2_lo(u64 v) { return __uint_as_float((unsigned)(v & 0xffffffffull)); }
__device__ __forceinline__ float ff2_hi(u64 v) { return __uint_as_float((unsigned)(v >> 32)); }

// ---------------- K0: PE table ----------------
__global__ void k_init_pe() {
    int s = threadIdx.x;              // 1024 threads
    int p0 = s >> 5, p1 = s & 31;
    int j = p1 >> 1;
    float freq = powf(1000.0f, -(float)j * (1.0f / 64.0f));
    float arg = 3.14159265358979323846f * (float)p0 * freq;
    g_pe[s] = (p1 & 1) ? cosf(arg) : sinf(arg);
}

// ---------------- K1: qkv = pe[s]*(x @ W^T) + b, scattered into q/k/v ----------------
// grid (1024, 3), block 256.  Tile: BM=128 rows, BF=128 cols, BK=16.
__global__ __launch_bounds__(256) void k_qkv(const float* __restrict__ x,
                                             const float* __restrict__ W,
                                             const float* __restrict__ bias) {
    __shared__ __align__(16) float As[16][128];
    __shared__ __align__(16) float Bs[16][128];
    const int mb = blockIdx.x * 128;
    const int fb = blockIdx.y * 128;
    const int tid = threadIdx.x;
    const int tx = tid & 15, ty = tid >> 4;
    const int mloc = ty * 8, floc = tx * 8;

    u64 acc[8][4] = {};

    for (int kb = 0; kb < 128; kb += 16) {
        #pragma unroll
        for (int l = tid; l < 512; l += 256) {
            int row = l >> 2; int k4 = (l & 3) << 2;
            float4 va = *reinterpret_cast<const float4*>(x + (size_t)(mb + row) * 128 + kb + k4);
            As[k4 + 0][row] = va.x; As[k4 + 1][row] = va.y;
            As[k4 + 2][row] = va.z; As[k4 + 3][row] = va.w;
            float4 vb = *reinterpret_cast<const float4*>(W + (size_t)(fb + row) * 128 + kb + k4);
            Bs[k4 + 0][row] = vb.x; Bs[k4 + 1][row] = vb.y;
            Bs[k4 + 2][row] = vb.z; Bs[k4 + 3][row] = vb.w;
        }
        __syncthreads();
        #pragma unroll
        for (int k = 0; k < 16; k++) {
            const u64* bp = reinterpret_cast<const u64*>(&Bs[k][floc]);
            u64 b0 = bp[0], b1 = bp[1], b2 = bp[2], b3 = bp[3];
            const float* ap = &As[k][mloc];
            #pragma unroll
            for (int i = 0; i < 8; i++) {
                u64 aa = ff2_pack(ap[i], ap[i]);
                ff2_fma(acc[i][0], aa, b0);
                ff2_fma(acc[i][1], aa, b1);
                ff2_fma(acc[i][2], aa, b2);
                ff2_fma(acc[i][3], aa, b3);
            }
        }
        __syncthreads();
    }

    float bb[8];
    *reinterpret_cast<float4*>(&bb[0]) = *reinterpret_cast<const float4*>(bias + fb + floc);
    *reinterpret_cast<float4*>(&bb[4]) = *reinterpret_cast<const float4*>(bias + fb + floc + 4);

    #pragma unroll
    for (int i = 0; i < 8; i++) {
        int r = mb + mloc + i;
        float p = g_pe[r & 1023];
        size_t base = (size_t)r * 128;
        #pragma unroll
        for (int j = 0; j < 4; j++) {
            float v0 = fmaf(p, ff2_lo(acc[i][j]), bb[2 * j]);
            float v1 = fmaf(p, ff2_hi(acc[i][j]), bb[2 * j + 1]);
            int f0 = fb + floc + 2 * j;
            int g0 = f0 / 3, s0 = f0 - 3 * g0;
            if (s0 == 0) g_q[base + g0] = v0; else if (s0 == 1) g_k[base + g0] = v0; else g_v[base + g0] = v0;
            int f1 = f0 + 1;
            int g1 = f1 / 3, s1 = f1 - 3 * g1;
            if (s1 == 0) g_q[base + g1] = v1; else if (s1 == 1) g_k[base + g1] = v1; else g_v[base + g1] = v1;
        }
    }
}

// ---------------- K2: split-K partial scores; grid 256 (K-chunks of 512), block 256 ----------------
__global__ __launch_bounds__(256) void k_scores() {
    __shared__ __align__(16) float Qs[16][128];
    __shared__ __align__(16) float Ks[16][128];
    const int tid = threadIdx.x;
    const int tx = tid & 15, ty = tid >> 4;
    const int n2loc = tx * 8, nloc = ty * 8;
    const int cb = blockIdx.x * 512;

    u64 acc[8][4] = {};

    for (int st = 0; st < 32; ++st) {
        int c0 = cb + st * 16;
        #pragma unroll
        for (int l = tid; l < 512; l += 256) {
            int row = l >> 2; int k4 = (l & 3) << 2;
            float4 vq = *reinterpret_cast<const float4*>(g_q + (size_t)row * 131072 + c0 + k4);
            Qs[k4 + 0][row] = vq.x; Qs[k4 + 1][row] = vq.y;
            Qs[k4 + 2][row] = vq.z; Qs[k4 + 3][row] = vq.w;
            float4 vk = *reinterpret_cast<const float4*>(g_k + (size_t)row * 131072 + c0 + k4);
            Ks[k4 + 0][row] = vk.x; Ks[k4 + 1][row] = vk.y;
            Ks[k4 + 2][row] = vk.z; Ks[k4 + 3][row] = vk.w;
        }
        __syncthreads();
        #pragma unroll
        for (int t = 0; t < 16; t++) {
            const u64* bp = reinterpret_cast<const u64*>(&Ks[t][n2loc]);
            u64 b0 = bp[0], b1 = bp[1], b2 = bp[2], b3 = bp[3];
            const float* ap = &Qs[t][nloc];
            #pragma unroll
            for (int i = 0; i < 8; i++) {
                u64 aa = ff2_pack(ap[i], ap[i]);
                ff2_fma(acc[i][0], aa, b0);
                ff2_fma(acc[i][1], aa, b1);
                ff2_fma(acc[i][2], aa, b2);
                ff2_fma(acc[i][3], aa, b3);
            }
        }
        __syncthreads();
    }

    float* outp = g_spart + (size_t)blockIdx.x * 16384;
    #pragma unroll
    for (int i = 0; i < 8; i++) {
        float4 o0 = make_float4(ff2_lo(acc[i][0]), ff2_hi(acc[i][0]),
                                ff2_lo(acc[i][1]), ff2_hi(acc[i][1]));
        float4 o1 = make_float4(ff2_lo(acc[i][2]), ff2_hi(acc[i][2]),
                                ff2_lo(acc[i][3]), ff2_hi(acc[i][3]));
        *reinterpret_cast<float4*>(outp + (nloc + i) * 128 + n2loc)     = o0;
        *reinterpret_cast<float4*>(outp + (nloc + i) * 128 + n2loc + 4) = o1;
    }
}

// ---------------- K3: deterministic reduction of partials ----------------
__global__ void k_reduce() {
    int idx = blockIdx.x * 256 + threadIdx.x;   // grid 64
    float s0 = 0.f, s1 = 0.f, s2 = 0.f, s3 = 0.f;
    for (int p = 0; p < 256; p += 4) {
        s0 += g_spart[(size_t)(p + 0) * 16384 + idx];
        s1 += g_spart[(size_t)(p + 1) * 16384 + idx];
        s2 += g_spart[(size_t)(p + 2) * 16384 + idx];
        s3 += g_spart[(size_t)(p + 3) * 16384 + idx];
    }
    g_scores[idx] = (s0 + s1) + (s2 + s3);
}

// ---------------- K4: softmax (rows) + write transposed attn ----------------
__global__ void k_softmax() {
    int n = threadIdx.x;   // 128 threads, 1 block
    const float rs = 0.0883883476483184405f;   // 1/sqrt(128)
    const float* row = g_scores + n * 128;
    float mx = -1e30f;
    for (int j = 0; j < 128; j++) mx = fmaxf(mx, row[j]);
    float m = mx * rs;
    float sum = 0.f;
    for (int j = 0; j < 128; j++) sum += expf(row[j] * rs - m);
    float inv = 1.0f / sum;
    for (int j = 0; j < 128; j++) g_attnT[j * 128 + n] = expf(row[j] * rs - m) * inv;
}

// ---------------- K5: out = attn @ v ; grid (1024, 2), block 256 ----------------
__global__ __launch_bounds__(256) void k_out(float* __restrict__ out) {
    __shared__ __align__(16) float AtS[128][64];
    __shared__ __align__(16) float Vs[16][128];
    const int tid = threadIdx.x;
    const int tx = tid & 15, ty = tid >> 4;
    const int cloc = tx * 8, nloc = ty * 4;
    const int cb = blockIdx.x * 128;
    const int nb = blockIdx.y * 64;

    // Load attnT slice: all k=128, n in [nb, nb+64)
    #pragma unroll
    for (int l = tid; l < 2048; l += 256) {
        int k = l >> 4; int n4 = (l & 15) << 2;
        float4 v = *reinterpret_cast<const float4*>(g_attnT + k * 128 + nb + n4);
        *reinterpret_cast<float4*>(&AtS[k][n4]) = v;
    }

    u64 acc[4][4] = {};

    for (int st = 0; st < 8; ++st) {
        #pragma unroll
        for (int l = tid; l < 512; l += 256) {
            int t = l >> 5; int c4 = (l & 31) << 2;
            float4 v = *reinterpret_cast<const float4*>(g_v + (size_t)(st * 16 + t) * 131072 + cb + c4);
            *reinterpret_cast<float4*>(&Vs[t][c4]) = v;
        }
        __syncthreads();
        #pragma unroll
        for (int t = 0; t < 16; t++) {
            const u64* bp = reinterpret_cast<const u64*>(&Vs[t][cloc]);
            u64 b0 = bp[0], b1 = bp[1], b2 = bp[2], b3 = bp[3];
            const float* ap = &AtS[st * 16 + t][nloc];
            #pragma unroll
            for (int i = 0; i < 4; i++) {
                u64 aa = ff2_pack(ap[i], ap[i]);
                ff2_fma(acc[i][0], aa, b0);
                ff2_fma(acc[i][1], aa, b1);
                ff2_fma(acc[i][2], aa, b2);
                ff2_fma(acc[i][3], aa, b3);
            }
        }
        __syncthreads();
    }

    #pragma unroll
    for (int i = 0; i < 4; i++) {
        size_t base = (size_t)(nb + nloc + i) * 131072 + cb + cloc;
        float4 o0 = make_float4(ff2_lo(acc[i][0]), ff2_hi(acc[i][0]),
                                ff2_lo(acc[i][1]), ff2_hi(acc[i][1]));
        float4 o1 = make_float4(ff2_lo(acc[i][2]), ff2_hi(acc[i][2]),
                                ff2_lo(acc[i][3]), ff2_hi(acc[i][3]));
        *reinterpret_cast<float4*>(out + base)     = o0;
        *reinterpret_cast<float4*>(out + base + 4) = o1;
    }
}

// ---------------- launch ----------------
extern "C" void kernel_launch(void* const* d_in, const int* in_sizes, int n_in,
                              void* d_out, int out_size) {
    const float* x = nullptr; const float* W = nullptr; const float* b = nullptr;
    for (int i = 0; i < n_in; i++) {
        if      (in_sizes[i] == 16777216) x = (const float*)d_in[i];
        else if (in_sizes[i] == 49152)    W = (const float*)d_in[i];
        else if (in_sizes[i] == 384)      b = (const float*)d_in[i];
    }
    if (!x) x = (const float*)d_in[0];
    if (!W) W = (const float*)d_in[1];
    if (!b) b = (const float*)d_in[2];
    float* out = (float*)d_out;

    k_init_pe<<<1, 1024>>>();
    k_qkv<<<dim3(1024, 3), 256>>>(x, W, b);
    k_scores<<<256, 256>>>();
    k_reduce<<<64, 256>>>();
    k_softmax<<<1, 128>>>();
    k_out<<<dim3(1024, 2), 256>>>(out);
}

// round 3
// speedup vs baseline: 1.2911x; 1.2911x over previous
#include <cuda_runtime.h>

typedef unsigned long long u64;

// ---------------- scratch ----------------
__device__ float g_T[16777216];          // T[r][d] = (A x_r), r = m*1024+s
__device__ float g_xb[16777216];         // xbar[n][c]
__device__ float g_spart[256 * 16384];
__device__ float g_scores[16384];
__device__ float g_attnT[16384];
__device__ float g_pe[1024];
__device__ float g_pe2[1024];
__device__ float g_AT[16384];            // AT[e][d] = A[d][e] = sum_g Wq[g,d] Wk[g,e]
__device__ float g_WvT[16384];           // WvT[d][g] = Wv[g][d]
__device__ float g_bv[128];
__device__ float g_u[128];
__device__ float g_w[128];
__device__ float g_c[16384];             // c[n][d]
__device__ float g_alpha[128];
__device__ float g_beta[128];
__device__ float g_gamma;

// ---------------- f32x2 helpers ----------------
__device__ __forceinline__ u64 ff2_pack(float lo, float hi) {
    u64 r; asm("mov.b64 %0, {%1, %2};" : "=l"(r) : "f"(lo), "f"(hi)); return r;
}
__device__ __forceinline__ void ff2_fma(u64 &d, u64 a, u64 b) {
    asm("fma.rn.f32x2 %0, %1, %2, %0;" : "+l"(d) : "l"(a), "l"(b));
}
__device__ __forceinline__ float ff2_lo(u64 v) { return __uint_as_float((unsigned)(v & 0xffffffffull)); }
__device__ __forceinline__ float ff2_hi(u64 v) { return __uint_as_float((unsigned)(v >> 32)); }

// one k-step: acc[4 M-pairs][8 N] += Apair * Bbroadcast
__device__ __forceinline__ void tile_step(u64 (&acc)[4][8], const float* Ap, const float* Bp) {
    u64 a[4];
    #pragma unroll
    for (int i = 0; i < 4; i++) a[i] = *(const u64*)(Ap + 2 * i);
    float4 b0 = *(const float4*)(Bp);
    float4 b1 = *(const float4*)(Bp + 4);
    u64 bp[8];
    bp[0] = ff2_pack(b0.x, b0.x); bp[1] = ff2_pack(b0.y, b0.y);
    bp[2] = ff2_pack(b0.z, b0.z); bp[3] = ff2_pack(b0.w, b0.w);
    bp[4] = ff2_pack(b1.x, b1.x); bp[5] = ff2_pack(b1.y, b1.y);
    bp[6] = ff2_pack(b1.z, b1.z); bp[7] = ff2_pack(b1.w, b1.w);
    #pragma unroll
    for (int i = 0; i < 4; i++)
        #pragma unroll
        for (int j = 0; j < 8; j++)
            ff2_fma(acc[i][j], a[i], bp[j]);
}

// staging with stride 130 (A-side only, u64 reads)
__device__ __forceinline__ void stage8_130(float* dst, float4 r0, float4 r1) {
    dst[0]   = r0.x; dst[130] = r0.y; dst[260] = r0.z; dst[390] = r0.w;
    dst[520] = r1.x; dst[650] = r1.y; dst[780] = r1.z; dst[910] = r1.w;
}
// staging with stride 132 (used when float4 reads hit the buffer)
__device__ __forceinline__ void stage8_132(float* dst, float4 r0, float4 r1) {
    dst[0]   = r0.x; dst[132] = r0.y; dst[264] = r0.z; dst[396] = r0.w;
    dst[528] = r1.x; dst[660] = r1.y; dst[792] = r1.z; dst[924] = r1.w;
}

// ---------------- K0: PE tables ----------------
__global__ void k_init_pe() {
    int s = threadIdx.x;
    int p0 = s >> 5, p1 = s & 31;
    int j = p1 >> 1;
    float freq = powf(1000.0f, -(float)j * (1.0f / 64.0f));
    float arg = 3.14159265358979323846f * (float)p0 * freq;
    float v = (p1 & 1) ? cosf(arg) : sinf(arg);
    g_pe[s] = v;
    g_pe2[s] = v * v;
}

// ---------------- K1: AT[e][d] = sum_g Wq[g,d] Wk[g,e]; WvT ----------------
__global__ void k_prep(const float* __restrict__ W) {
    __shared__ float wqd[128];
    int d = blockIdx.x, e = threadIdx.x;
    wqd[e] = W[384 * e + d];                 // Wq[g=e, d]
    __syncthreads();
    float acc = 0.f;
    #pragma unroll 4
    for (int g = 0; g < 128; g++) acc += wqd[g] * W[384 * g + 128 + e];
    g_AT[e * 128 + d] = acc;
    g_WvT[d * 128 + e] = W[384 * e + 256 + d];   // Wv[g=e, d]
}

// ---------------- K2: u, w, bv, gamma ----------------
__global__ void k_prep2(const float* __restrict__ W, const float* __restrict__ b) {
    int d = threadIdx.x;   // 128 threads
    float au = 0.f, aw = 0.f;
    #pragma unroll 4
    for (int g = 0; g < 128; g++) {
        au += W[384 * g + d]       * b[3 * g + 1];
        aw += W[384 * g + 128 + d] * b[3 * g];
    }
    g_u[d] = au;
    g_w[d] = aw;
    g_bv[d] = b[3 * d + 2];
    if (d == 0) {
        float gg = 0.f;
        for (int g = 0; g < 128; g++) gg += b[3 * g] * b[3 * g + 1];
        g_gamma = 1024.0f * gg;
    }
}

// ---------------- K3: c[n][d] = sum_s pe[s] x[n,s,d] ----------------
__global__ void k_c(const float* __restrict__ x) {
    int n = blockIdx.x, d = threadIdx.x;
    const float* xp = x + (size_t)n * 131072 + d;
    float a0 = 0.f, a1 = 0.f, a2 = 0.f, a3 = 0.f;
    for (int s = 0; s < 1024; s += 4) {
        a0 += g_pe[s]     * xp[(size_t)s * 128];
        a1 += g_pe[s + 1] * xp[(size_t)(s + 1) * 128];
        a2 += g_pe[s + 2] * xp[(size_t)(s + 2) * 128];
        a3 += g_pe[s + 3] * xp[(size_t)(s + 3) * 128];
    }
    g_c[n * 128 + d] = (a0 + a1) + (a2 + a3);
}

// ---------------- K4: alpha[n] = c_n . u ; beta[n] = c_n . w ----------------
__global__ void k_ab() {
    int n = threadIdx.x;
    float a = 0.f, bb = 0.f;
    #pragma unroll 4
    for (int d = 0; d < 128; d++) {
        float cv = g_c[n * 128 + d];
        a  += cv * g_u[d];
        bb += cv * g_w[d];
    }
    g_alpha[n] = a;
    g_beta[n]  = bb;
}

// ---------------- K5: T = X @ A^T  (T[r][d] = sum_e X[r,e] AT[e][d]) ----------------
__global__ void __launch_bounds__(256, 2) k_T(const float* __restrict__ X) {
    extern __shared__ float dsm[];
    float* Bs = dsm;                 // [e*128 + d]  (16384)
    float* As = dsm + 16384;         // [buf*2080 + e*130 + row]
    const int tid = threadIdx.x;
    const int mb = blockIdx.x * 128;
    const int tx = tid & 15, ty = tid >> 4;
    const int mloc = ty * 8, nloc = tx * 8;

    #pragma unroll
    for (int i = 0; i < 16; i++) {
        int off = i * 1024 + tid * 4;
        *(float4*)(Bs + off) = *(const float4*)(g_AT + off);
    }

    const int srow = tid >> 1, shalf = tid & 1;
    const float* xrow = X + (size_t)(mb + srow) * 128 + shalf * 8;

    float4 r0 = *(const float4*)(xrow);
    float4 r1 = *(const float4*)(xrow + 4);
    stage8_130(As + (shalf * 8) * 130 + srow, r0, r1);
    __syncthreads();

    u64 acc[4][8];
    #pragma unroll
    for (int i = 0; i < 4; i++)
        #pragma unroll
        for (int j = 0; j < 8; j++) acc[i][j] = 0ull;

    for (int kb = 0; kb < 8; kb++) {
        if (kb < 7) {
            r0 = *(const float4*)(xrow + (kb + 1) * 16);
            r1 = *(const float4*)(xrow + (kb + 1) * 16 + 4);
        }
        const float* Ab = As + (kb & 1) * 2080;
        #pragma unroll
        for (int k = 0; k < 16; k++)
            tile_step(acc, Ab + k * 130 + mloc, Bs + (kb * 16 + k) * 128 + nloc);
        if (kb < 7) {
            stage8_130(As + ((kb + 1) & 1) * 2080 + (shalf * 8) * 130 + srow, r0, r1);
            __syncthreads();
        }
    }

    #pragma unroll
    for (int i = 0; i < 4; i++) {
        size_t row0 = (size_t)(mb + mloc + 2 * i) * 128;
        float4 lo0 = make_float4(ff2_lo(acc[i][0]), ff2_lo(acc[i][1]), ff2_lo(acc[i][2]), ff2_lo(acc[i][3]));
        float4 lo1 = make_float4(ff2_lo(acc[i][4]), ff2_lo(acc[i][5]), ff2_lo(acc[i][6]), ff2_lo(acc[i][7]));
        float4 hi0 = make_float4(ff2_hi(acc[i][0]), ff2_hi(acc[i][1]), ff2_hi(acc[i][2]), ff2_hi(acc[i][3]));
        float4 hi1 = make_float4(ff2_hi(acc[i][4]), ff2_hi(acc[i][5]), ff2_hi(acc[i][6]), ff2_hi(acc[i][7]));
        *(float4*)(g_T + row0 + nloc)           = lo0;
        *(float4*)(g_T + row0 + nloc + 4)       = lo1;
        *(float4*)(g_T + row0 + 128 + nloc)     = hi0;
        *(float4*)(g_T + row0 + 128 + nloc + 4) = hi1;
    }
}

// ---------------- K6: split-K scores: sum_c pe2[s(c)] X[n,c] T[m,c] ----------------
// stride-132 staging: B-side float4 reads at k*132 + nloc are 16B aligned.
__global__ void __launch_bounds__(256, 2) k_scores(const float* __restrict__ X) {
    __shared__ __align__(16) float Qs[2][2112];
    __shared__ __align__(16) float Ks[2][2112];
    const int tid = threadIdx.x;
    const int tx = tid & 15, ty = tid >> 4;
    const int mloc = ty * 8, nloc = tx * 8;     // n-rows, m-cols
    const int cb = blockIdx.x * 512;
    const int srow = tid >> 1, shalf = tid & 1;
    const float* qrow = X   + (size_t)srow * 131072 + cb + shalf * 8;
    const float* krow = g_T + (size_t)srow * 131072 + cb + shalf * 8;

    float w2 = g_pe2[cb >> 7];
    float4 q0 = *(const float4*)(qrow);
    float4 q1 = *(const float4*)(qrow + 4);
    float4 k0 = *(const float4*)(krow);
    float4 k1 = *(const float4*)(krow + 4);
    q0.x *= w2; q0.y *= w2; q0.z *= w2; q0.w *= w2;
    q1.x *= w2; q1.y *= w2; q1.z *= w2; q1.w *= w2;
    stage8_132(&Qs[0][(shalf * 8) * 132 + srow], q0, q1);
    stage8_132(&Ks[0][(shalf * 8) * 132 + srow], k0, k1);
    __syncthreads();

    u64 acc[4][8];
    #pragma unroll
    for (int i = 0; i < 4; i++)
        #pragma unroll
        for (int j = 0; j < 8; j++) acc[i][j] = 0ull;

    for (int st = 0; st < 32; st++) {
        if (st < 31) {
            int off = (st + 1) * 16;
            float w2n = g_pe2[(cb + off) >> 7];
            q0 = *(const float4*)(qrow + off);
            q1 = *(const float4*)(qrow + off + 4);
            k0 = *(const float4*)(krow + off);
            k1 = *(const float4*)(krow + off + 4);
            q0.x *= w2n; q0.y *= w2n; q0.z *= w2n; q0.w *= w2n;
            q1.x *= w2n; q1.y *= w2n; q1.z *= w2n; q1.w *= w2n;
        }
        const float* Qb = Qs[st & 1];
        const float* Kb = Ks[st & 1];
        #pragma unroll
        for (int k = 0; k < 16; k++)
            tile_step(acc, Qb + k * 132 + mloc, Kb + k * 132 + nloc);
        if (st < 31) {
            stage8_132(&Qs[(st + 1) & 1][(shalf * 8) * 132 + srow], q0, q1);
            stage8_132(&Ks[(st + 1) & 1][(shalf * 8) * 132 + srow], k0, k1);
            __syncthreads();
        }
    }

    float* outp = g_spart + (size_t)blockIdx.x * 16384;
    #pragma unroll
    for (int i = 0; i < 4; i++) {
        int row0 = (mloc + 2 * i) * 128;
        float4 lo0 = make_float4(ff2_lo(acc[i][0]), ff2_lo(acc[i][1]), ff2_lo(acc[i][2]), ff2_lo(acc[i][3]));
        float4 lo1 = make_float4(ff2_lo(acc[i][4]), ff2_lo(acc[i][5]), ff2_lo(acc[i][6]), ff2_lo(acc[i][7]));
        float4 hi0 = make_float4(ff2_hi(acc[i][0]), ff2_hi(acc[i][1]), ff2_hi(acc[i][2]), ff2_hi(acc[i][3]));
        float4 hi1 = make_float4(ff2_hi(acc[i][4]), ff2_hi(acc[i][5]), ff2_hi(acc[i][6]), ff2_hi(acc[i][7]));
        *(float4*)(outp + row0 + nloc)           = lo0;
        *(float4*)(outp + row0 + nloc + 4)       = lo1;
        *(float4*)(outp + row0 + 128 + nloc)     = hi0;
        *(float4*)(outp + row0 + 128 + nloc + 4) = hi1;
    }
}

// ---------------- K7: reduce partials + alpha/beta/gamma ----------------
__global__ void k_reduce() {
    int idx = blockIdx.x * 256 + threadIdx.x;   // grid 64
    float s[8] = {0.f, 0.f, 0.f, 0.f, 0.f, 0.f, 0.f, 0.f};
    for (int p = 0; p < 256; p += 8) {
        #pragma unroll
        for (int j = 0; j < 8; j++) s[j] += g_spart[(size_t)(p + j) * 16384 + idx];
    }
    float tot = ((s[0] + s[1]) + (s[2] + s[3])) + ((s[4] + s[5]) + (s[6] + s[7]));
    int n = idx >> 7, m = idx & 127;
    g_scores[idx] = tot + g_alpha[n] + g_beta[m] + g_gamma;
}

// ---------------- K8: softmax + transpose ----------------
__global__ void k_softmax() {
    int n = threadIdx.x;
    const float rs = 0.0883883476483184405f;   // 1/sqrt(128)
    const float* row = g_scores + n * 128;
    float mx = -1e30f;
    for (int j = 0; j < 128; j++) mx = fmaxf(mx, row[j]);
    float m = mx * rs;
    float sum = 0.f;
    for (int j = 0; j < 128; j++) sum += expf(row[j] * rs - m);
    float inv = 1.0f / sum;
    for (int j = 0; j < 128; j++) g_attnT[j * 128 + n] = expf(row[j] * rs - m) * inv;
}

// ---------------- K9: xbar[n][c] = sum_m attn[n,m] X[m,c] ----------------
__global__ void __launch_bounds__(256, 2) k_xbar(const float* __restrict__ X) {
    extern __shared__ float dsm[];
    float* At  = dsm;            // attnT resident: [m*128 + n]  (16384)
    float* Bst = dsm + 16384;    // [buf*2048 + mlocal*128 + col]
    const int tid = threadIdx.x;
    const int cb = blockIdx.x * 128;
    const int tx = tid & 15, ty = tid >> 4;
    const int mloc = ty * 8, nloc = tx * 8;   // n-rows, c-cols

    #pragma unroll
    for (int i = 0; i < 16; i++) {
        int off = i * 1024 + tid * 4;
        *(float4*)(At + off) = *(const float4*)(g_attnT + off);
    }

    const int mrow = tid >> 4;            // 0..15
    const int col  = (tid & 15) * 8;
    const float* xbase = X + cb + col;

    float4 r0 = *(const float4*)(xbase + (size_t)mrow * 131072);
    float4 r1 = *(const float4*)(xbase + (size_t)mrow * 131072 + 4);
    *(float4*)(Bst + mrow * 128 + col)     = r0;
    *(float4*)(Bst + mrow * 128 + col + 4) = r1;
    __syncthreads();

    u64 acc[4][8];
    #pragma unroll
    for (int i = 0; i < 4; i++)
        #pragma unroll
        for (int j = 0; j < 8; j++) acc[i][j] = 0ull;

    for (int kb = 0; kb < 8; kb++) {
        if (kb < 7) {
            size_t g = (size_t)((kb + 1) * 16 + mrow) * 131072;
            r0 = *(const float4*)(xbase + g);
            r1 = *(const float4*)(xbase + g + 4);
        }
        const float* Bb = Bst + (kb & 1) * 2048;
        #pragma unroll
        for (int k = 0; k < 16; k++)
            tile_step(acc, At + (kb * 16 + k) * 128 + mloc, Bb + k * 128 + nloc);
        if (kb < 7) {
            float* d = Bst + ((kb + 1) & 1) * 2048 + mrow * 128 + col;
            *(float4*)(d)     = r0;
            *(float4*)(d + 4) = r1;
            __syncthreads();
        }
    }

    #pragma unroll
    for (int i = 0; i < 4; i++) {
        size_t row0 = (size_t)(mloc + 2 * i) * 131072 + cb;
        float4 lo0 = make_float4(ff2_lo(acc[i][0]), ff2_lo(acc[i][1]), ff2_lo(acc[i][2]), ff2_lo(acc[i][3]));
        float4 lo1 = make_float4(ff2_lo(acc[i][4]), ff2_lo(acc[i][5]), ff2_lo(acc[i][6]), ff2_lo(acc[i][7]));
        float4 hi0 = make_float4(ff2_hi(acc[i][0]), ff2_hi(acc[i][1]), ff2_hi(acc[i][2]), ff2_hi(acc[i][3]));
        float4 hi1 = make_float4(ff2_hi(acc[i][4]), ff2_hi(acc[i][5]), ff2_hi(acc[i][6]), ff2_hi(acc[i][7]));
        *(float4*)(g_xb + row0 + nloc)              = lo0;
        *(float4*)(g_xb + row0 + nloc + 4)          = lo1;
        *(float4*)(g_xb + row0 + 131072 + nloc)     = hi0;
        *(float4*)(g_xb + row0 + 131072 + nloc + 4) = hi1;
    }
}

// ---------------- K10: out[r][g] = pe[s] * sum_d xbar[r,d] WvT[d,g] + bv[g] ----------------
__global__ void __launch_bounds__(256, 2) k_out2(float* __restrict__ out) {
    extern __shared__ float dsm[];
    float* Bs = dsm;                 // WvT resident [d*128 + g]
    float* As = dsm + 16384;
    const int tid = threadIdx.x;
    const int mb = blockIdx.x * 128;
    const int tx = tid & 15, ty = tid >> 4;
    const int mloc = ty * 8, nloc = tx * 8;

    #pragma unroll
    for (int i = 0; i < 16; i++) {
        int off = i * 1024 + tid * 4;
        *(float4*)(Bs + off) = *(const float4*)(g_WvT + off);
    }

    const int srow = tid >> 1, shalf = tid & 1;
    const float* xrow = g_xb + (size_t)(mb + srow) * 128 + shalf * 8;

    float4 r0 = *(const float4*)(xrow);
    float4 r1 = *(const float4*)(xrow + 4);
    stage8_130(As + (shalf * 8) * 130 + srow, r0, r1);
    __syncthreads();

    u64 acc[4][8];
    #pragma unroll
    for (int i = 0; i < 4; i++)
        #pragma unroll
        for (int j = 0; j < 8; j++) acc[i][j] = 0ull;

    for (int kb = 0; kb < 8; kb++) {
        if (kb < 7) {
            r0 = *(const float4*)(xrow + (kb + 1) * 16);
            r1 = *(const float4*)(xrow + (kb + 1) * 16 + 4);
        }
        const float* Ab = As + (kb & 1) * 2080;
        #pragma unroll
        for (int k = 0; k < 16; k++)
            tile_step(acc, Ab + k * 130 + mloc, Bs + (kb * 16 + k) * 128 + nloc);
        if (kb < 7) {
            stage8_130(As + ((kb + 1) & 1) * 2080 + (shalf * 8) * 130 + srow, r0, r1);
            __syncthreads();
        }
    }

    float4 bva = *(const float4*)(g_bv + nloc);
    float4 bvb = *(const float4*)(g_bv + nloc + 4);

    #pragma unroll
    for (int i = 0; i < 4; i++) {
        int r0i = mb + mloc + 2 * i;
        float p0 = g_pe[r0i & 1023];
        float p1 = g_pe[(r0i + 1) & 1023];
        float4 o;
        size_t base0 = (size_t)r0i * 128 + nloc;
        o = make_float4(fmaf(p0, ff2_lo(acc[i][0]), bva.x), fmaf(p0, ff2_lo(acc[i][1]), bva.y),
                        fmaf(p0, ff2_lo(acc[i][2]), bva.z), fmaf(p0, ff2_lo(acc[i][3]), bva.w));
        *(float4*)(out + base0) = o;
        o = make_float4(fmaf(p0, ff2_lo(acc[i][4]), bvb.x), fmaf(p0, ff2_lo(acc[i][5]), bvb.y),
                        fmaf(p0, ff2_lo(acc[i][6]), bvb.z), fmaf(p0, ff2_lo(acc[i][7]), bvb.w));
        *(float4*)(out + base0 + 4) = o;
        size_t base1 = base0 + 128;
        o = make_float4(fmaf(p1, ff2_hi(acc[i][0]), bva.x), fmaf(p1, ff2_hi(acc[i][1]), bva.y),
                        fmaf(p1, ff2_hi(acc[i][2]), bva.z), fmaf(p1, ff2_hi(acc[i][3]), bva.w));
        *(float4*)(out + base1) = o;
        o = make_float4(fmaf(p1, ff2_hi(acc[i][4]), bvb.x), fmaf(p1, ff2_hi(acc[i][5]), bvb.y),
                        fmaf(p1, ff2_hi(acc[i][6]), bvb.z), fmaf(p1, ff2_hi(acc[i][7]), bvb.w));
        *(float4*)(out + base1 + 4) = o;
    }
}

// ---------------- launch ----------------
extern "C" void kernel_launch(void* const* d_in, const int* in_sizes, int n_in,
                              void* d_out, int out_size) {
    const float* x = nullptr; const float* W = nullptr; const float* b = nullptr;
    for (int i = 0; i < n_in; i++) {
        if      (in_sizes[i] == 16777216) x = (const float*)d_in[i];
        else if (in_sizes[i] == 49152)    W = (const float*)d_in[i];
        else if (in_sizes[i] == 384)      b = (const float*)d_in[i];
    }
    if (!x) x = (const float*)d_in[0];
    if (!W) W = (const float*)d_in[1];
    if (!b) b = (const float*)d_in[2];
    float* out = (float*)d_out;

    cudaFuncSetAttribute(k_T,    cudaFuncAttributeMaxDynamicSharedMemorySize, 82176);
    cudaFuncSetAttribute(k_xbar, cudaFuncAttributeMaxDynamicSharedMemorySize, 81920);
    cudaFuncSetAttribute(k_out2, cudaFuncAttributeMaxDynamicSharedMemorySize, 82176);

    k_init_pe<<<1, 1024>>>();
    k_prep<<<128, 128>>>(W);
    k_prep2<<<1, 128>>>(W, b);
    k_c<<<128, 128>>>(x);
    k_ab<<<1, 128>>>();
    k_T<<<1024, 256, 82176>>>(x);
    k_scores<<<256, 256>>>(x);
    k_reduce<<<64, 256>>>();
    k_softmax<<<1, 128>>>();
    k_xbar<<<1024, 256, 81920>>>(x);
    k_out2<<<1024, 256, 82176>>>(out);
}

// round 4
// speedup vs baseline: 1.3936x; 1.0794x over previous
#include <cuda_runtime.h>

typedef unsigned long long u64;

// ---------------- scratch ----------------
__device__ float g_xb[16777216];         // xbar[n][c]
__device__ float g_spart[256 * 16384];   // partial score tiles (128 used)
__device__ float g_scores[16384];        // [128][128]
__device__ float g_attnT[16384];
__device__ float g_pe[1024];
__device__ float g_A[16384];             // A[d][e] = sum_g Wq[g,d] Wk[g,e]
__device__ float g_WvT[16384];           // WvT[d][g] = Wv[g][d]
__device__ float g_bv[128];
__device__ float g_u[128];
__device__ float g_w[128];
__device__ float g_cpart[8 * 16384];     // c partials over s-chunks
__device__ float g_c[16384];             // c[n][d]
__device__ float g_alpha[128];
__device__ float g_beta[128];
__device__ float g_gamma;

// ---------------- f32x2 helpers ----------------
__device__ __forceinline__ u64 ff2_pack(float lo, float hi) {
    u64 r; asm("mov.b64 %0, {%1, %2};" : "=l"(r) : "f"(lo), "f"(hi)); return r;
}
__device__ __forceinline__ void ff2_fma(u64 &d, u64 a, u64 b) {
    asm("fma.rn.f32x2 %0, %1, %2, %0;" : "+l"(d) : "l"(a), "l"(b));
}
__device__ __forceinline__ float ff2_lo(u64 v) { return __uint_as_float((unsigned)(v & 0xffffffffull)); }
__device__ __forceinline__ float ff2_hi(u64 v) { return __uint_as_float((unsigned)(v >> 32)); }

// one k-step: acc[4 row-pairs][8 cols] += Apair * Bbroadcast
__device__ __forceinline__ void tile_step(u64 (&acc)[4][8], const float* Ap, const float* Bp) {
    u64 a[4];
    #pragma unroll
    for (int i = 0; i < 4; i++) a[i] = *(const u64*)(Ap + 2 * i);
    float4 b0 = *(const float4*)(Bp);
    float4 b1 = *(const float4*)(Bp + 4);
    u64 bp[8];
    bp[0] = ff2_pack(b0.x, b0.x); bp[1] = ff2_pack(b0.y, b0.y);
    bp[2] = ff2_pack(b0.z, b0.z); bp[3] = ff2_pack(b0.w, b0.w);
    bp[4] = ff2_pack(b1.x, b1.x); bp[5] = ff2_pack(b1.y, b1.y);
    bp[6] = ff2_pack(b1.z, b1.z); bp[7] = ff2_pack(b1.w, b1.w);
    #pragma unroll
    for (int i = 0; i < 4; i++)
        #pragma unroll
        for (int j = 0; j < 8; j++)
            ff2_fma(acc[i][j], a[i], bp[j]);
}

// staging with stride 130 (A-side only, u64 reads)
__device__ __forceinline__ void stage8_130(float* dst, float4 r0, float4 r1) {
    dst[0]   = r0.x; dst[130] = r0.y; dst[260] = r0.z; dst[390] = r0.w;
    dst[520] = r1.x; dst[650] = r1.y; dst[780] = r1.z; dst[910] = r1.w;
}

// ---------------- K0: PE table ----------------
__global__ void k_init_pe() {
    int s = threadIdx.x;
    int p0 = s >> 5, p1 = s & 31;
    int j = p1 >> 1;
    float freq = powf(1000.0f, -(float)j * (1.0f / 64.0f));
    float arg = 3.14159265358979323846f * (float)p0 * freq;
    g_pe[s] = (p1 & 1) ? cosf(arg) : sinf(arg);
}

// ---------------- K1: A[d][e] = sum_g Wq[g,d] Wk[g,e]; WvT ----------------
__global__ void k_prep(const float* __restrict__ W) {
    __shared__ float wqd[128];
    int d = blockIdx.x, e = threadIdx.x;
    wqd[e] = W[384 * e + d];                 // Wq[g=e, d]
    __syncthreads();
    float acc = 0.f;
    #pragma unroll 4
    for (int g = 0; g < 128; g++) acc += wqd[g] * W[384 * g + 128 + e];
    g_A[d * 128 + e] = acc;                  // A[d][e]
    g_WvT[d * 128 + e] = W[384 * e + 256 + d];
}

// ---------------- K2: u, w, bv, gamma ----------------
__global__ void k_prep2(const float* __restrict__ W, const float* __restrict__ b) {
    int d = threadIdx.x;
    float au = 0.f, aw = 0.f;
    #pragma unroll 4
    for (int g = 0; g < 128; g++) {
        au += W[384 * g + d]       * b[3 * g + 1];
        aw += W[384 * g + 128 + d] * b[3 * g];
    }
    g_u[d] = au;
    g_w[d] = aw;
    g_bv[d] = b[3 * d + 2];
    if (d == 0) {
        float gg = 0.f;
        for (int g = 0; g < 128; g++) gg += b[3 * g] * b[3 * g + 1];
        g_gamma = 1024.0f * gg;
    }
}

// ---------------- K3: c partials, grid (128 n, 8 chunks), block 128 ----------------
__global__ void k_c(const float* __restrict__ x) {
    int n = blockIdx.x, ck = blockIdx.y, d = threadIdx.x;
    int s0 = ck * 128;
    const float* xp = x + ((size_t)n * 1024 + s0) * 128 + d;
    float a0 = 0.f, a1 = 0.f, a2 = 0.f, a3 = 0.f;
    for (int s = 0; s < 128; s += 4) {
        a0 += g_pe[s0 + s]     * xp[(size_t)s * 128];
        a1 += g_pe[s0 + s + 1] * xp[(size_t)(s + 1) * 128];
        a2 += g_pe[s0 + s + 2] * xp[(size_t)(s + 2) * 128];
        a3 += g_pe[s0 + s + 3] * xp[(size_t)(s + 3) * 128];
    }
    g_cpart[ck * 16384 + n * 128 + d] = (a0 + a1) + (a2 + a3);
}

// ---------------- K3b: sum c partials ----------------
__global__ void k_csum() {
    int i = blockIdx.x * 256 + threadIdx.x;   // grid 64
    float s = 0.f;
    #pragma unroll
    for (int ck = 0; ck < 8; ck++) s += g_cpart[ck * 16384 + i];
    g_c[i] = s;
}

// ---------------- K4: alpha[n] = c_n . u ; beta[n] = c_n . w ----------------
__global__ void k_ab() {
    int n = threadIdx.x;
    float a = 0.f, bb = 0.f;
    #pragma unroll 4
    for (int d = 0; d < 128; d++) {
        float cv = g_c[n * 128 + d];
        a  += cv * g_u[d];
        bb += cv * g_w[d];
    }
    g_alpha[n] = a;
    g_beta[n]  = bb;
}

// ---------------- K5: fused scores: per s, (pe Xs) A (pe Xs)^T ----------------
// grid 128 blocks (8 s each), block 256. smem: A(16384) + Xst(16896) + Ust(16896).
__global__ void __launch_bounds__(256) k_fused(const float* __restrict__ X) {
    extern __shared__ float dsm[];
    float* Asm = dsm;             // [d*128 + e]
    float* Xst = dsm + 16384;     // [d*132 + n]  (pe-scaled X transposed)
    float* Ust = dsm + 33280;     // [e*132 + n]
    const int tid = threadIdx.x;
    const int tx = tid & 15, ty = tid >> 4;
    const int rloc = ty * 8, cloc = tx * 8;

    #pragma unroll
    for (int i = 0; i < 16; i++) {
        int off = i * 1024 + tid * 4;
        *(float4*)(Asm + off) = *(const float4*)(g_A + off);
    }

    const int nrow = tid >> 1, half = tid & 1;

    u64 sacc[4][8];
    #pragma unroll
    for (int i = 0; i < 4; i++)
        #pragma unroll
        for (int j = 0; j < 8; j++) sacc[i][j] = 0ull;

    for (int s = 0; s < 8; s++) {
        int sg = blockIdx.x * 8 + s;
        float p = g_pe[sg];
        __syncthreads();
        // load Xs (pe-scaled, transposed): thread owns row nrow, cols [half*64, half*64+64)
        const float* src = X + ((size_t)nrow * 1024 + sg) * 128 + half * 64;
        #pragma unroll
        for (int i = 0; i < 16; i++) {
            float4 v = *(const float4*)(src + i * 4);
            int d0 = half * 64 + i * 4;
            Xst[(d0 + 0) * 132 + nrow] = v.x * p;
            Xst[(d0 + 1) * 132 + nrow] = v.y * p;
            Xst[(d0 + 2) * 132 + nrow] = v.z * p;
            Xst[(d0 + 3) * 132 + nrow] = v.w * p;
        }
        __syncthreads();

        // phase 1: Ust[e][n] = sum_d Asm[d][e] * Xst[d][n]
        u64 ua[4][8];
        #pragma unroll
        for (int i = 0; i < 4; i++)
            #pragma unroll
            for (int j = 0; j < 8; j++) ua[i][j] = 0ull;
        #pragma unroll 16
        for (int d = 0; d < 128; d++)
            tile_step(ua, Asm + d * 128 + rloc, Xst + d * 132 + cloc);

        #pragma unroll
        for (int i = 0; i < 4; i++) {
            int e0 = rloc + 2 * i;
            float4 lo0 = make_float4(ff2_lo(ua[i][0]), ff2_lo(ua[i][1]), ff2_lo(ua[i][2]), ff2_lo(ua[i][3]));
            float4 lo1 = make_float4(ff2_lo(ua[i][4]), ff2_lo(ua[i][5]), ff2_lo(ua[i][6]), ff2_lo(ua[i][7]));
            float4 hi0 = make_float4(ff2_hi(ua[i][0]), ff2_hi(ua[i][1]), ff2_hi(ua[i][2]), ff2_hi(ua[i][3]));
            float4 hi1 = make_float4(ff2_hi(ua[i][4]), ff2_hi(ua[i][5]), ff2_hi(ua[i][6]), ff2_hi(ua[i][7]));
            *(float4*)(Ust + e0 * 132 + cloc)             = lo0;
            *(float4*)(Ust + e0 * 132 + cloc + 4)         = lo1;
            *(float4*)(Ust + (e0 + 1) * 132 + cloc)       = hi0;
            *(float4*)(Ust + (e0 + 1) * 132 + cloc + 4)   = hi1;
        }
        __syncthreads();

        // phase 2: sacc[n][m] += sum_e Ust[e][n] * Xst[e][m]
        #pragma unroll 16
        for (int e = 0; e < 128; e++)
            tile_step(sacc, Ust + e * 132 + rloc, Xst + e * 132 + cloc);
    }

    float* outp = g_spart + (size_t)blockIdx.x * 16384;
    #pragma unroll
    for (int i = 0; i < 4; i++) {
        int row0 = (rloc + 2 * i) * 128;
        float4 lo0 = make_float4(ff2_lo(sacc[i][0]), ff2_lo(sacc[i][1]), ff2_lo(sacc[i][2]), ff2_lo(sacc[i][3]));
        float4 lo1 = make_float4(ff2_lo(sacc[i][4]), ff2_lo(sacc[i][5]), ff2_lo(sacc[i][6]), ff2_lo(sacc[i][7]));
        float4 hi0 = make_float4(ff2_hi(sacc[i][0]), ff2_hi(sacc[i][1]), ff2_hi(sacc[i][2]), ff2_hi(sacc[i][3]));
        float4 hi1 = make_float4(ff2_hi(sacc[i][4]), ff2_hi(sacc[i][5]), ff2_hi(sacc[i][6]), ff2_hi(sacc[i][7]));
        *(float4*)(outp + row0 + cloc)           = lo0;
        *(float4*)(outp + row0 + cloc + 4)       = lo1;
        *(float4*)(outp + row0 + 128 + cloc)     = hi0;
        *(float4*)(outp + row0 + 128 + cloc + 4) = hi1;
    }
}

// ---------------- K6: reduce 128 partials (float4) + alpha/beta/gamma ----------------
__global__ void k_reduce() {
    int f = blockIdx.x * 256 + threadIdx.x;   // grid 16; f in [0,4096)
    float4 a0 = make_float4(0.f, 0.f, 0.f, 0.f), a1 = a0, a2 = a0, a3 = a0;
    for (int p = 0; p < 128; p += 4) {
        float4 v0 = *(const float4*)(g_spart + (size_t)(p + 0) * 16384 + 4 * f);
        float4 v1 = *(const float4*)(g_spart + (size_t)(p + 1) * 16384 + 4 * f);
        float4 v2 = *(const float4*)(g_spart + (size_t)(p + 2) * 16384 + 4 * f);
        float4 v3 = *(const float4*)(g_spart + (size_t)(p + 3) * 16384 + 4 * f);
        a0.x += v0.x; a0.y += v0.y; a0.z += v0.z; a0.w += v0.w;
        a1.x += v1.x; a1.y += v1.y; a1.z += v1.z; a1.w += v1.w;
        a2.x += v2.x; a2.y += v2.y; a2.z += v2.z; a2.w += v2.w;
        a3.x += v3.x; a3.y += v3.y; a3.z += v3.z; a3.w += v3.w;
    }
    float4 tot = make_float4((a0.x + a1.x) + (a2.x + a3.x), (a0.y + a1.y) + (a2.y + a3.y),
                             (a0.z + a1.z) + (a2.z + a3.z), (a0.w + a1.w) + (a2.w + a3.w));
    int n = f >> 5;             // (4f)>>7
    int m0 = (4 * f) & 127;
    float al = g_alpha[n], gm = g_gamma;
    float4 be = *(const float4*)(g_beta + m0);
    float4 o = make_float4(tot.x + al + be.x + gm, tot.y + al + be.y + gm,
                           tot.z + al + be.z + gm, tot.w + al + be.w + gm);
    *(float4*)(g_scores + 4 * f) = o;
}

// ---------------- K7: softmax + transpose ----------------
__global__ void k_softmax() {
    int n = threadIdx.x;
    const float rs = 0.0883883476483184405f;   // 1/sqrt(128)
    const float* row = g_scores + n * 128;
    float mx = -1e30f;
    for (int j = 0; j < 128; j++) mx = fmaxf(mx, row[j]);
    float m = mx * rs;
    float sum = 0.f;
    for (int j = 0; j < 128; j++) sum += expf(row[j] * rs - m);
    float inv = 1.0f / sum;
    for (int j = 0; j < 128; j++) g_attnT[j * 128 + n] = expf(row[j] * rs - m) * inv;
}

// ---------------- K8: xbar[n][c] = sum_m attn[n,m] X[m,c] ----------------
__global__ void __launch_bounds__(256, 2) k_xbar(const float* __restrict__ X) {
    extern __shared__ float dsm[];
    float* At  = dsm;            // attnT resident: [m*128 + n]
    float* Bst = dsm + 16384;    // [buf*2048 + mlocal*128 + col]
    const int tid = threadIdx.x;
    const int cb = blockIdx.x * 128;
    const int tx = tid & 15, ty = tid >> 4;
    const int mloc = ty * 8, nloc = tx * 8;

    #pragma unroll
    for (int i = 0; i < 16; i++) {
        int off = i * 1024 + tid * 4;
        *(float4*)(At + off) = *(const float4*)(g_attnT + off);
    }

    const int mrow = tid >> 4;
    const int col  = (tid & 15) * 8;
    const float* xbase = X + cb + col;

    float4 r0 = *(const float4*)(xbase + (size_t)mrow * 131072);
    float4 r1 = *(const float4*)(xbase + (size_t)mrow * 131072 + 4);
    *(float4*)(Bst + mrow * 128 + col)     = r0;
    *(float4*)(Bst + mrow * 128 + col + 4) = r1;
    __syncthreads();

    u64 acc[4][8];
    #pragma unroll
    for (int i = 0; i < 4; i++)
        #pragma unroll
        for (int j = 0; j < 8; j++) acc[i][j] = 0ull;

    for (int kb = 0; kb < 8; kb++) {
        if (kb < 7) {
            size_t g = (size_t)((kb + 1) * 16 + mrow) * 131072;
            r0 = *(const float4*)(xbase + g);
            r1 = *(const float4*)(xbase + g + 4);
        }
        const float* Bb = Bst + (kb & 1) * 2048;
        #pragma unroll
        for (int k = 0; k < 16; k++)
            tile_step(acc, At + (kb * 16 + k) * 128 + mloc, Bb + k * 128 + nloc);
        if (kb < 7) {
            float* d = Bst + ((kb + 1) & 1) * 2048 + mrow * 128 + col;
            *(float4*)(d)     = r0;
            *(float4*)(d + 4) = r1;
            __syncthreads();
        }
    }

    #pragma unroll
    for (int i = 0; i < 4; i++) {
        size_t row0 = (size_t)(mloc + 2 * i) * 131072 + cb;
        float4 lo0 = make_float4(ff2_lo(acc[i][0]), ff2_lo(acc[i][1]), ff2_lo(acc[i][2]), ff2_lo(acc[i][3]));
        float4 lo1 = make_float4(ff2_lo(acc[i][4]), ff2_lo(acc[i][5]), ff2_lo(acc[i][6]), ff2_lo(acc[i][7]));
        float4 hi0 = make_float4(ff2_hi(acc[i][0]), ff2_hi(acc[i][1]), ff2_hi(acc[i][2]), ff2_hi(acc[i][3]));
        float4 hi1 = make_float4(ff2_hi(acc[i][4]), ff2_hi(acc[i][5]), ff2_hi(acc[i][6]), ff2_hi(acc[i][7]));
        *(float4*)(g_xb + row0 + nloc)              = lo0;
        *(float4*)(g_xb + row0 + nloc + 4)          = lo1;
        *(float4*)(g_xb + row0 + 131072 + nloc)     = hi0;
        *(float4*)(g_xb + row0 + 131072 + nloc + 4) = hi1;
    }
}

// ---------------- K9: out[r][g] = pe[s] * sum_d xbar[r,d] WvT[d,g] + bv[g] ----------------
__global__ void __launch_bounds__(256, 2) k_out2(float* __restrict__ out) {
    extern __shared__ float dsm[];
    float* Bs = dsm;                 // WvT resident [d*128 + g]
    float* As = dsm + 16384;
    const int tid = threadIdx.x;
    const int mb = blockIdx.x * 128;
    const int tx = tid & 15, ty = tid >> 4;
    const int mloc = ty * 8, nloc = tx * 8;

    #pragma unroll
    for (int i = 0; i < 16; i++) {
        int off = i * 1024 + tid * 4;
        *(float4*)(Bs + off) = *(const float4*)(g_WvT + off);
    }

    const int srow = tid >> 1, shalf = tid & 1;
    const float* xrow = g_xb + (size_t)(mb + srow) * 128 + shalf * 8;

    float4 r0 = *(const float4*)(xrow);
    float4 r1 = *(const float4*)(xrow + 4);
    stage8_130(As + (shalf * 8) * 130 + srow, r0, r1);
    __syncthreads();

    u64 acc[4][8];
    #pragma unroll
    for (int i = 0; i < 4; i++)
        #pragma unroll
        for (int j = 0; j < 8; j++) acc[i][j] = 0ull;

    for (int kb = 0; kb < 8; kb++) {
        if (kb < 7) {
            r0 = *(const float4*)(xrow + (kb + 1) * 16);
            r1 = *(const float4*)(xrow + (kb + 1) * 16 + 4);
        }
        const float* Ab = As + (kb & 1) * 2080;
        #pragma unroll
        for (int k = 0; k < 16; k++)
            tile_step(acc, Ab + k * 130 + mloc, Bs + (kb * 16 + k) * 128 + nloc);
        if (kb < 7) {
            stage8_130(As + ((kb + 1) & 1) * 2080 + (shalf * 8) * 130 + srow, r0, r1);
            __syncthreads();
        }
    }

    float4 bva = *(const float4*)(g_bv + nloc);
    float4 bvb = *(const float4*)(g_bv + nloc + 4);

    #pragma unroll
    for (int i = 0; i < 4; i++) {
        int r0i = mb + mloc + 2 * i;
        float p0 = g_pe[r0i & 1023];
        float p1 = g_pe[(r0i + 1) & 1023];
        float4 o;
        size_t base0 = (size_t)r0i * 128 + nloc;
        o = make_float4(fmaf(p0, ff2_lo(acc[i][0]), bva.x), fmaf(p0, ff2_lo(acc[i][1]), bva.y),
                        fmaf(p0, ff2_lo(acc[i][2]), bva.z), fmaf(p0, ff2_lo(acc[i][3]), bva.w));
        *(float4*)(out + base0) = o;
        o = make_float4(fmaf(p0, ff2_lo(acc[i][4]), bvb.x), fmaf(p0, ff2_lo(acc[i][5]), bvb.y),
                        fmaf(p0, ff2_lo(acc[i][6]), bvb.z), fmaf(p0, ff2_lo(acc[i][7]), bvb.w));
        *(float4*)(out + base0 + 4) = o;
        size_t base1 = base0 + 128;
        o = make_float4(fmaf(p1, ff2_hi(acc[i][0]), bva.x), fmaf(p1, ff2_hi(acc[i][1]), bva.y),
                        fmaf(p1, ff2_hi(acc[i][2]), bva.z), fmaf(p1, ff2_hi(acc[i][3]), bva.w));
        *(float4*)(out + base1) = o;
        o = make_float4(fmaf(p1, ff2_hi(acc[i][4]), bvb.x), fmaf(p1, ff2_hi(acc[i][5]), bvb.y),
                        fmaf(p1, ff2_hi(acc[i][6]), bvb.z), fmaf(p1, ff2_hi(acc[i][7]), bvb.w));
        *(float4*)(out + base1 + 4) = o;
    }
}

// ---------------- launch ----------------
extern "C" void kernel_launch(void* const* d_in, const int* in_sizes, int n_in,
                              void* d_out, int out_size) {
    const float* x = nullptr; const float* W = nullptr; const float* b = nullptr;
    for (int i = 0; i < n_in; i++) {
        if      (in_sizes[i] == 16777216) x = (const float*)d_in[i];
        else if (in_sizes[i] == 49152)    W = (const float*)d_in[i];
        else if (in_sizes[i] == 384)      b = (const float*)d_in[i];
    }
    if (!x) x = (const float*)d_in[0];
    if (!W) W = (const float*)d_in[1];
    if (!b) b = (const float*)d_in[2];
    float* out = (float*)d_out;

    cudaFuncSetAttribute(k_fused, cudaFuncAttributeMaxDynamicSharedMemorySize, 200704);
    cudaFuncSetAttribute(k_xbar,  cudaFuncAttributeMaxDynamicSharedMemorySize, 81920);
    cudaFuncSetAttribute(k_out2,  cudaFuncAttributeMaxDynamicSharedMemorySize, 82176);

    k_init_pe<<<1, 1024>>>();
    k_prep<<<128, 128>>>(W);
    k_prep2<<<1, 128>>>(W, b);
    k_c<<<dim3(128, 8), 128>>>(x);
    k_csum<<<64, 256>>>();
    k_ab<<<1, 128>>>();
    k_fused<<<128, 256, 200704>>>(x);
    k_reduce<<<16, 256>>>();
    k_softmax<<<1, 128>>>();
    k_xbar<<<1024, 256, 81920>>>(x);
    k_out2<<<1024, 256, 82176>>>(out);
}

// round 7
// speedup vs baseline: 1.7673x; 1.2682x over previous
#include <cuda_runtime.h>
#include <cuda_bf16.h>

typedef unsigned long long u64;
typedef unsigned int u32;

// ---------------- scratch ----------------
__device__ float g_spart[128 * 16384];
__device__ float g_scores[16384];
__device__ float g_attnT[16384];
__device__ float g_pe[1024];
__device__ float g_A[16384];             // A[d][e] = sum_g Wq[g,d] Wk[g,e]
__device__ float g_bv[128];
__device__ float g_u[128];
__device__ float g_w[128];
__device__ float g_cpart[8 * 16384];
__device__ float g_c[16384];
__device__ float g_alpha[128];
__device__ float g_beta[128];
__device__ float g_gamma;

// bf16 hi/lo tensors
__device__ __align__(16) __nv_bfloat16 g_Yhi[16777216];
__device__ __align__(16) __nv_bfloat16 g_Ylo[16777216];
__device__ __align__(16) __nv_bfloat16 g_Zhi[16777216];
__device__ __align__(16) __nv_bfloat16 g_Zlo[16777216];
__device__ __align__(16) __nv_bfloat16 g_xbhi[16777216];
__device__ __align__(16) __nv_bfloat16 g_xblo[16777216];
// padded operand images [128][136]
__device__ __align__(16) __nv_bfloat16 g_Aophi[17408];
__device__ __align__(16) __nv_bfloat16 g_Aoplo[17408];
__device__ __align__(16) __nv_bfloat16 g_Wvophi[17408];
__device__ __align__(16) __nv_bfloat16 g_Wvoplo[17408];

// ---------------- helpers ----------------
__device__ __forceinline__ u32 smem_u32(const void* p) {
    u32 a; asm("{ .reg .u64 t; cvta.to.shared.u64 t, %1; cvt.u32.u64 %0, t; }" : "=r"(a) : "l"(p));
    return a;
}
__device__ __forceinline__ void cp16(u32 dst, const void* src) {
    asm volatile("cp.async.cg.shared.global [%0], [%1], 16;" :: "r"(dst), "l"(src));
}
__device__ __forceinline__ void cp_commit() { asm volatile("cp.async.commit_group;" ::: "memory"); }
template<int N> __device__ __forceinline__ void cp_wait() {
    asm volatile("cp.async.wait_group %0;" :: "n"(N) : "memory");
}

__device__ __forceinline__ void mma16816(float* c, const u32* a, const u32* b) {
    asm volatile("mma.sync.aligned.m16n8k16.row.col.f32.bf16.bf16.f32 "
        "{%0,%1,%2,%3}, {%4,%5,%6,%7}, {%8,%9}, {%0,%1,%2,%3};"
        : "+f"(c[0]), "+f"(c[1]), "+f"(c[2]), "+f"(c[3])
        : "r"(a[0]), "r"(a[1]), "r"(a[2]), "r"(a[3]), "r"(b[0]), "r"(b[1]));
}

__device__ __forceinline__ void pack_hilo(float a, float b, u32& hp, u32& lp) {
    __nv_bfloat16 ha = __float2bfloat16(a), hb = __float2bfloat16(b);
    float ra = a - __bfloat162float(ha), rb = b - __bfloat162float(hb);
    __nv_bfloat16 la = __float2bfloat16(ra), lb = __float2bfloat16(rb);
    hp = (u32)__bfloat16_as_ushort(ha) | ((u32)__bfloat16_as_ushort(hb) << 16);
    lp = (u32)__bfloat16_as_ushort(la) | ((u32)__bfloat16_as_ushort(lb) << 16);
}

// one product: C[128x128] += A[128xK] * B[128xK]^T, tiles padded to SW u32 words/row
template<int KC, int SW>
__device__ __forceinline__ void gemm_prod(float (&acc)[2][8][4], const u32* As, const u32* Bs,
                                          int wm, int wn, int g, int t) {
    #pragma unroll
    for (int kc = 0; kc < KC; kc++) {
        const int kw = kc * 8;
        u32 a[2][4];
        #pragma unroll
        for (int i = 0; i < 2; i++) {
            int rb = wm * 32 + i * 16;
            a[i][0] = As[(rb + g) * SW + kw + t];
            a[i][1] = As[(rb + g + 8) * SW + kw + t];
            a[i][2] = As[(rb + g) * SW + kw + t + 4];
            a[i][3] = As[(rb + g + 8) * SW + kw + t + 4];
        }
        u32 b[8][2];
        #pragma unroll
        for (int j = 0; j < 8; j++) {
            int rb = wn * 64 + j * 8;
            b[j][0] = Bs[(rb + g) * SW + kw + t];
            b[j][1] = Bs[(rb + g) * SW + kw + t + 4];
        }
        #pragma unroll
        for (int i = 0; i < 2; i++)
            #pragma unroll
            for (int j = 0; j < 8; j++)
                mma16816(acc[i][j], a[i], b[j]);
    }
}

// ---------------- f32x2 (k_xbar scalar path) ----------------
__device__ __forceinline__ u64 ff2_pack(float lo, float hi) {
    u64 r; asm("mov.b64 %0, {%1, %2};" : "=l"(r) : "f"(lo), "f"(hi)); return r;
}
__device__ __forceinline__ void ff2_fma(u64 &d, u64 a, u64 b) {
    asm("fma.rn.f32x2 %0, %1, %2, %0;" : "+l"(d) : "l"(a), "l"(b));
}
__device__ __forceinline__ float ff2_lo(u64 v) { return __uint_as_float((unsigned)(v & 0xffffffffull)); }
__device__ __forceinline__ float ff2_hi(u64 v) { return __uint_as_float((unsigned)(v >> 32)); }

__device__ __forceinline__ void tile_step(u64 (&acc)[4][8], const float* Ap, const float* Bp) {
    u64 a[4];
    #pragma unroll
    for (int i = 0; i < 4; i++) a[i] = *(const u64*)(Ap + 2 * i);
    float4 b0 = *(const float4*)(Bp);
    float4 b1 = *(const float4*)(Bp + 4);
    u64 bp[8];
    bp[0] = ff2_pack(b0.x, b0.x); bp[1] = ff2_pack(b0.y, b0.y);
    bp[2] = ff2_pack(b0.z, b0.z); bp[3] = ff2_pack(b0.w, b0.w);
    bp[4] = ff2_pack(b1.x, b1.x); bp[5] = ff2_pack(b1.y, b1.y);
    bp[6] = ff2_pack(b1.z, b1.z); bp[7] = ff2_pack(b1.w, b1.w);
    #pragma unroll
    for (int i = 0; i < 4; i++)
        #pragma unroll
        for (int j = 0; j < 8; j++)
            ff2_fma(acc[i][j], a[i], bp[j]);
}

// ---------------- K0: PE table ----------------
__global__ void k_init_pe() {
    int s = threadIdx.x;
    int p0 = s >> 5, p1 = s & 31;
    int j = p1 >> 1;
    float freq = powf(1000.0f, -(float)j * (1.0f / 64.0f));
    float arg = 3.14159265358979323846f * (float)p0 * freq;
    g_pe[s] = (p1 & 1) ? cosf(arg) : sinf(arg);
}

// ---------------- K1: A[d][e] ----------------
__global__ void k_prep(const float* __restrict__ W) {
    __shared__ float wqd[128];
    int d = blockIdx.x, e = threadIdx.x;
    wqd[e] = W[384 * e + d];
    __syncthreads();
    float acc = 0.f;
    #pragma unroll 4
    for (int g = 0; g < 128; g++) acc += wqd[g] * W[384 * g + 128 + e];
    g_A[d * 128 + e] = acc;
}

// ---------------- K1b: padded bf16 operand images ----------------
__global__ void k_prepA(const float* __restrict__ W) {
    int e = blockIdx.x, d = threadIdx.x;
    float a = g_A[d * 128 + e];                 // Aop[e][d] = A[d][e]
    __nv_bfloat16 h = __float2bfloat16(a);
    __nv_bfloat16 l = __float2bfloat16(a - __bfloat162float(h));
    g_Aophi[e * 136 + d] = h;
    g_Aoplo[e * 136 + d] = l;
    float wv = W[384 * e + 256 + d];            // Wv[g=e][d]
    __nv_bfloat16 hw = __float2bfloat16(wv);
    __nv_bfloat16 lw = __float2bfloat16(wv - __bfloat162float(hw));
    g_Wvophi[e * 136 + d] = hw;
    g_Wvoplo[e * 136 + d] = lw;
}

// ---------------- K2: u, w, bv, gamma ----------------
__global__ void k_prep2(const float* __restrict__ W, const float* __restrict__ b) {
    int d = threadIdx.x;
    float au = 0.f, aw = 0.f;
    #pragma unroll 4
    for (int g = 0; g < 128; g++) {
        au += W[384 * g + d]       * b[3 * g + 1];
        aw += W[384 * g + 128 + d] * b[3 * g];
    }
    g_u[d] = au;
    g_w[d] = aw;
    g_bv[d] = b[3 * d + 2];
    if (d == 0) {
        float gg = 0.f;
        for (int g = 0; g < 128; g++) gg += b[3 * g] * b[3 * g + 1];
        g_gamma = 1024.0f * gg;
    }
}

// ---------------- K3: c partials + sum + alpha/beta ----------------
__global__ void k_c(const float* __restrict__ x) {
    int n = blockIdx.x, ck = blockIdx.y, d = threadIdx.x;
    int s0 = ck * 128;
    const float* xp = x + ((size_t)n * 1024 + s0) * 128 + d;
    float a0 = 0.f, a1 = 0.f, a2 = 0.f, a3 = 0.f;
    for (int s = 0; s < 128; s += 4) {
        a0 += g_pe[s0 + s]     * xp[(size_t)s * 128];
        a1 += g_pe[s0 + s + 1] * xp[(size_t)(s + 1) * 128];
        a2 += g_pe[s0 + s + 2] * xp[(size_t)(s + 2) * 128];
        a3 += g_pe[s0 + s + 3] * xp[(size_t)(s + 3) * 128];
    }
    g_cpart[ck * 16384 + n * 128 + d] = (a0 + a1) + (a2 + a3);
}
__global__ void k_csum() {
    int i = blockIdx.x * 256 + threadIdx.x;
    float s = 0.f;
    #pragma unroll
    for (int ck = 0; ck < 8; ck++) s += g_cpart[ck * 16384 + i];
    g_c[i] = s;
}
__global__ void k_ab() {
    int n = threadIdx.x;
    float a = 0.f, bb = 0.f;
    #pragma unroll 4
    for (int d = 0; d < 128; d++) {
        float cv = g_c[n * 128 + d];
        a  += cv * g_u[d];
        bb += cv * g_w[d];
    }
    g_alpha[n] = a;
    g_beta[n]  = bb;
}

// ---------------- K5: k_yz — Y = (pe X) Aop^T, Z = pe X  (mma.sync bf16) ----------------
// grid 1024, 256 thr. smem: Xhi(34816) Xlo Ahi Alo = 139264 B
__global__ void __launch_bounds__(256) k_yz(const float* __restrict__ X) {
    extern __shared__ __align__(16) unsigned char sm[];
    u32* Xhi = (u32*)sm;
    u32* Xlo = (u32*)(sm + 34816);
    u32* Ahi = (u32*)(sm + 69632);
    u32* Alo = (u32*)(sm + 104448);
    const int tid = threadIdx.x;
    const int rbase = blockIdx.x * 128;

    for (int i = tid; i < 2176; i += 256) {
        ((uint4*)Ahi)[i] = ((const uint4*)g_Aophi)[i];
        ((uint4*)Alo)[i] = ((const uint4*)g_Aoplo)[i];
    }
    #pragma unroll
    for (int i = 0; i < 16; i++) {
        int idx = tid + i * 256;
        int row = idx >> 5, jc = idx & 31;
        int r = rbase + row;
        float p = g_pe[r & 1023];
        float4 v = *(const float4*)(X + (size_t)r * 128 + jc * 4);
        u32 h0, l0, h1, l1;
        pack_hilo(v.x * p, v.y * p, h0, l0);
        pack_hilo(v.z * p, v.w * p, h1, l1);
        ((uint2*)Xhi)[row * 34 + jc] = make_uint2(h0, h1);
        ((uint2*)Xlo)[row * 34 + jc] = make_uint2(l0, l1);
        *(uint2*)(g_Zhi + (size_t)r * 128 + jc * 4) = make_uint2(h0, h1);
        *(uint2*)(g_Zlo + (size_t)r * 128 + jc * 4) = make_uint2(l0, l1);
    }
    __syncthreads();

    const int lane = tid & 31, warp = tid >> 5;
    const int wm = warp >> 1, wn = warp & 1, g = lane >> 2, t = lane & 3;
    float acc[2][8][4];
    #pragma unroll
    for (int i = 0; i < 2; i++)
        #pragma unroll
        for (int j = 0; j < 8; j++)
            #pragma unroll
            for (int q = 0; q < 4; q++) acc[i][j][q] = 0.f;

    gemm_prod<8, 68>(acc, Xhi, Ahi, wm, wn, g, t);
    gemm_prod<8, 68>(acc, Xhi, Alo, wm, wn, g, t);
    gemm_prod<8, 68>(acc, Xlo, Ahi, wm, wn, g, t);

    #pragma unroll
    for (int i = 0; i < 2; i++) {
        int r0 = rbase + wm * 32 + i * 16 + g;
        #pragma unroll
        for (int j = 0; j < 8; j++) {
            int e0 = wn * 64 + j * 8 + 2 * t;
            u32 h, l;
            pack_hilo(acc[i][j][0], acc[i][j][1], h, l);
            *(u32*)(g_Yhi + (size_t)r0 * 128 + e0) = h;
            *(u32*)(g_Ylo + (size_t)r0 * 128 + e0) = l;
            pack_hilo(acc[i][j][2], acc[i][j][3], h, l);
            *(u32*)(g_Yhi + (size_t)(r0 + 8) * 128 + e0) = h;
            *(u32*)(g_Ylo + (size_t)(r0 + 8) * 128 + e0) = l;
        }
    }
}

// ---------------- K6: k_sc — score partials = Y . Z^T (split-K, mma.sync) ----------------
// grid 128, 256 thr. smem: 2 buffers x (Yhi Ylo Zhi Zlo)[128][72] = 147456 B
__global__ void __launch_bounds__(256) k_sc() {
    extern __shared__ __align__(16) unsigned char sm[];
    u32 smb = smem_u32(sm);
    const int tid = threadIdx.x;

    const int lane = tid & 31, warp = tid >> 5;
    const int wm = warp >> 1, wn = warp & 1, g = lane >> 2, t = lane & 3;

    #define SC_ISSUE(it, buf) do {                                                   \
        size_t c0 = (size_t)blockIdx.x * 1024 + (size_t)(it) * 64;                   \
        for (int q = 0; q < 4; q++) {                                                \
            int idx = tid + q * 256;                                                 \
            int row = idx >> 3, jc = idx & 7;                                        \
            u32 d = smb + (buf) * 73728 + row * 144 + jc * 16;                       \
            size_t go = (size_t)row * 131072 + c0 + (size_t)jc * 8;                  \
            cp16(d,          g_Yhi + go);                                            \
            cp16(d + 18432,  g_Ylo + go);                                            \
            cp16(d + 36864,  g_Zhi + go);                                            \
            cp16(d + 55296,  g_Zlo + go);                                            \
        }                                                                            \
        cp_commit();                                                                 \
    } while (0)

    float acc[2][8][4];
    #pragma unroll
    for (int i = 0; i < 2; i++)
        #pragma unroll
        for (int j = 0; j < 8; j++)
            #pragma unroll
            for (int q = 0; q < 4; q++) acc[i][j][q] = 0.f;

    SC_ISSUE(0, 0);
    for (int it = 0; it < 16; it++) {
        if (it < 15) SC_ISSUE(it + 1, (it + 1) & 1);
        if (it < 15) cp_wait<1>(); else cp_wait<0>();
        __syncthreads();
        unsigned char* base = sm + (it & 1) * 73728;
        const u32* Yh = (const u32*)(base);
        const u32* Yl = (const u32*)(base + 18432);
        const u32* Zh = (const u32*)(base + 36864);
        const u32* Zl = (const u32*)(base + 55296);
        gemm_prod<4, 36>(acc, Yh, Zh, wm, wn, g, t);
        gemm_prod<4, 36>(acc, Yh, Zl, wm, wn, g, t);
        gemm_prod<4, 36>(acc, Yl, Zh, wm, wn, g, t);
        __syncthreads();
    }

    float* outp = g_spart + (size_t)blockIdx.x * 16384;
    #pragma unroll
    for (int i = 0; i < 2; i++) {
        int n0 = wm * 32 + i * 16 + g;
        #pragma unroll
        for (int j = 0; j < 8; j++) {
            int m0 = wn * 64 + j * 8 + 2 * t;
            *(float2*)(outp + n0 * 128 + m0)       = make_float2(acc[i][j][0], acc[i][j][1]);
            *(float2*)(outp + (n0 + 8) * 128 + m0) = make_float2(acc[i][j][2], acc[i][j][3]);
        }
    }
}

// ---------------- K7: reduce partials + alpha/beta/gamma ----------------
__global__ void k_reduce() {
    int f = blockIdx.x * 256 + threadIdx.x;   // grid 16
    float4 a0 = make_float4(0.f, 0.f, 0.f, 0.f), a1 = a0, a2 = a0, a3 = a0;
    for (int p = 0; p < 128; p += 4) {
        float4 v0 = *(const float4*)(g_spart + (size_t)(p + 0) * 16384 + 4 * f);
        float4 v1 = *(const float4*)(g_spart + (size_t)(p + 1) * 16384 + 4 * f);
        float4 v2 = *(const float4*)(g_spart + (size_t)(p + 2) * 16384 + 4 * f);
        float4 v3 = *(const float4*)(g_spart + (size_t)(p + 3) * 16384 + 4 * f);
        a0.x += v0.x; a0.y += v0.y; a0.z += v0.z; a0.w += v0.w;
        a1.x += v1.x; a1.y += v1.y; a1.z += v1.z; a1.w += v1.w;
        a2.x += v2.x; a2.y += v2.y; a2.z += v2.z; a2.w += v2.w;
        a3.x += v3.x; a3.y += v3.y; a3.z += v3.z; a3.w += v3.w;
    }
    float4 tot = make_float4((a0.x + a1.x) + (a2.x + a3.x), (a0.y + a1.y) + (a2.y + a3.y),
                             (a0.z + a1.z) + (a2.z + a3.z), (a0.w + a1.w) + (a2.w + a3.w));
    int n = f >> 5;
    int m0 = (4 * f) & 127;
    float al = g_alpha[n], gm = g_gamma;
    float4 be = *(const float4*)(g_beta + m0);
    *(float4*)(g_scores + 4 * f) = make_float4(tot.x + al + be.x + gm, tot.y + al + be.y + gm,
                                               tot.z + al + be.z + gm, tot.w + al + be.w + gm);
}

// ---------------- K8: softmax + transpose ----------------
__global__ void k_softmax() {
    int n = threadIdx.x;
    const float rs = 0.0883883476483184405f;
    const float* row = g_scores + n * 128;
    float mx = -1e30f;
    for (int j = 0; j < 128; j++) mx = fmaxf(mx, row[j]);
    float m = mx * rs;
    float sum = 0.f;
    for (int j = 0; j < 128; j++) sum += expf(row[j] * rs - m);
    float inv = 1.0f / sum;
    for (int j = 0; j < 128; j++) g_attnT[j * 128 + n] = expf(row[j] * rs - m) * inv;
}

// ---------------- K9: xbarpe = pe[s] * (attn @ X), bf16 hi/lo out (scalar f32x2) ----------------
__global__ void __launch_bounds__(256, 2) k_xbar(const float* __restrict__ X) {
    extern __shared__ float dsm[];
    float* At  = dsm;
    float* Bst = dsm + 16384;
    const int tid = threadIdx.x;
    const int cb = blockIdx.x * 128;
    const int tx = tid & 15, ty = tid >> 4;
    const int mloc = ty * 8, nloc = tx * 8;

    #pragma unroll
    for (int i = 0; i < 16; i++) {
        int off = i * 1024 + tid * 4;
        *(float4*)(At + off) = *(const float4*)(g_attnT + off);
    }

    const int mrow = tid >> 4;
    const int col  = (tid & 15) * 8;
    const float* xbase = X + cb + col;

    float4 r0 = *(const float4*)(xbase + (size_t)mrow * 131072);
    float4 r1 = *(const float4*)(xbase + (size_t)mrow * 131072 + 4);
    *(float4*)(Bst + mrow * 128 + col)     = r0;
    *(float4*)(Bst + mrow * 128 + col + 4) = r1;
    __syncthreads();

    u64 acc[4][8];
    #pragma unroll
    for (int i = 0; i < 4; i++)
        #pragma unroll
        for (int j = 0; j < 8; j++) acc[i][j] = 0ull;

    for (int kb = 0; kb < 8; kb++) {
        if (kb < 7) {
            size_t g = (size_t)((kb + 1) * 16 + mrow) * 131072;
            r0 = *(const float4*)(xbase + g);
            r1 = *(const float4*)(xbase + g + 4);
        }
        const float* Bb = Bst + (kb & 1) * 2048;
        #pragma unroll
        for (int k = 0; k < 16; k++)
            tile_step(acc, At + (kb * 16 + k) * 128 + mloc, Bb + k * 128 + nloc);
        if (kb < 7) {
            float* d = Bst + ((kb + 1) & 1) * 2048 + mrow * 128 + col;
            *(float4*)(d)     = r0;
            *(float4*)(d + 4) = r1;
            __syncthreads();
        }
    }

    float p = g_pe[blockIdx.x];   // column block = single s
    #pragma unroll
    for (int i = 0; i < 4; i++) {
        int n0 = mloc + 2 * i;
        u32 h[4], l[4], h2[4], l2[4];
        #pragma unroll
        for (int jj = 0; jj < 4; jj++) {
            pack_hilo(ff2_lo(acc[i][2 * jj]) * p, ff2_lo(acc[i][2 * jj + 1]) * p, h[jj], l[jj]);
            pack_hilo(ff2_hi(acc[i][2 * jj]) * p, ff2_hi(acc[i][2 * jj + 1]) * p, h2[jj], l2[jj]);
        }
        size_t o0 = (size_t)n0 * 131072 + cb + nloc;
        *(uint4*)(g_xbhi + o0) = make_uint4(h[0], h[1], h[2], h[3]);
        *(uint4*)(g_xblo + o0) = make_uint4(l[0], l[1], l[2], l[3]);
        size_t o1 = o0 + 131072;
        *(uint4*)(g_xbhi + o1) = make_uint4(h2[0], h2[1], h2[2], h2[3]);
        *(uint4*)(g_xblo + o1) = make_uint4(l2[0], l2[1], l2[2], l2[3]);
    }
}

// ---------------- K10: out = xbarpe @ Wv^T + bv (mma.sync) ----------------
// grid 1024, 256 thr. smem: Ahi Alo Bhi Blo (4 x 34816) = 139264; rows are 68 words (272 B)
__global__ void __launch_bounds__(256) k_out2(float* __restrict__ out) {
    extern __shared__ __align__(16) unsigned char sm[];
    u32 smb = smem_u32(sm);
    const int tid = threadIdx.x;
    const int rbase = blockIdx.x * 128;

    for (int i = tid; i < 2048; i += 256) {
        int row = i >> 4, jc = i & 15;
        u32 d = smb + row * 272 + jc * 16;       // FIXED: 68-word (272 B) row stride
        size_t go = (size_t)(rbase + row) * 128 + (size_t)jc * 8;
        cp16(d,          g_xbhi + go);
        cp16(d + 34816,  g_xblo + go);
    }
    for (int i = tid; i < 2176; i += 256) {
        cp16(smb + 69632 + i * 16,  ((const uint4*)g_Wvophi) + i);
        cp16(smb + 104448 + i * 16, ((const uint4*)g_Wvoplo) + i);
    }
    cp_commit();
    cp_wait<0>();
    __syncthreads();

    const u32* Ahi = (const u32*)(sm);
    const u32* Alo = (const u32*)(sm + 34816);
    const u32* Bhi = (const u32*)(sm + 69632);
    const u32* Blo = (const u32*)(sm + 104448);

    const int lane = tid & 31, warp = tid >> 5;
    const int wm = warp >> 1, wn = warp & 1, g = lane >> 2, t = lane & 3;
    float acc[2][8][4];
    #pragma unroll
    for (int i = 0; i < 2; i++)
        #pragma unroll
        for (int j = 0; j < 8; j++)
            #pragma unroll
            for (int q = 0; q < 4; q++) acc[i][j][q] = 0.f;

    gemm_prod<8, 68>(acc, Ahi, Bhi, wm, wn, g, t);
    gemm_prod<8, 68>(acc, Ahi, Blo, wm, wn, g, t);
    gemm_prod<8, 68>(acc, Alo, Bhi, wm, wn, g, t);

    #pragma unroll
    for (int i = 0; i < 2; i++) {
        int r0 = rbase + wm * 32 + i * 16 + g;
        #pragma unroll
        for (int j = 0; j < 8; j++) {
            int e0 = wn * 64 + j * 8 + 2 * t;
            float2 bp = *(const float2*)(g_bv + e0);
            *(float2*)(out + (size_t)r0 * 128 + e0) =
                make_float2(acc[i][j][0] + bp.x, acc[i][j][1] + bp.y);
            *(float2*)(out + (size_t)(r0 + 8) * 128 + e0) =
                make_float2(acc[i][j][2] + bp.x, acc[i][j][3] + bp.y);
        }
    }
}

// ---------------- launch ----------------
extern "C" void kernel_launch(void* const* d_in, const int* in_sizes, int n_in,
                              void* d_out, int out_size) {
    const float* x = nullptr; const float* W = nullptr; const float* b = nullptr;
    for (int i = 0; i < n_in; i++) {
        if      (in_sizes[i] == 16777216) x = (const float*)d_in[i];
        else if (in_sizes[i] == 49152)    W = (const float*)d_in[i];
        else if (in_sizes[i] == 384)      b = (const float*)d_in[i];
    }
    if (!x) x = (const float*)d_in[0];
    if (!W) W = (const float*)d_in[1];
    if (!b) b = (const float*)d_in[2];
    float* out = (float*)d_out;

    cudaFuncSetAttribute(k_yz,   cudaFuncAttributeMaxDynamicSharedMemorySize, 139264);
    cudaFuncSetAttribute(k_sc,   cudaFuncAttributeMaxDynamicSharedMemorySize, 147456);
    cudaFuncSetAttribute(k_xbar, cudaFuncAttributeMaxDynamicSharedMemorySize, 81920);
    cudaFuncSetAttribute(k_out2, cudaFuncAttributeMaxDynamicSharedMemorySize, 139264);

    k_init_pe<<<1, 1024>>>();
    k_prep<<<128, 128>>>(W);
    k_prepA<<<128, 128>>>(W);
    k_prep2<<<1, 128>>>(W, b);
    k_c<<<dim3(128, 8), 128>>>(x);
    k_csum<<<64, 256>>>();
    k_ab<<<1, 128>>>();
    k_yz<<<1024, 256, 139264>>>(x);
    k_sc<<<128, 256, 147456>>>();
    k_reduce<<<16, 256>>>();
    k_softmax<<<1, 128>>>();
    k_xbar<<<1024, 256, 81920>>>(x);
    k_out2<<<1024, 256, 139264>>>(out);
}

// round 8
// speedup vs baseline: 1.9250x; 1.0892x over previous
#include <cuda_runtime.h>
#include <cuda_bf16.h>

typedef unsigned long long u64;
typedef unsigned int u32;

// ---------------- scratch ----------------
__device__ float g_spart[128 * 16384];
__device__ float g_scores[16384];
__device__ float g_pe[1024];
__device__ float g_A[16384];             // A[d][e] = sum_g Wq[g,d] Wk[g,e]
__device__ float g_bv[128];
__device__ float g_u[128];
__device__ float g_w[128];
__device__ float g_cpart[8 * 16384];
__device__ float g_c[16384];
__device__ float g_alpha[128];
__device__ float g_beta[128];
__device__ float g_gamma;

// bf16 hi/lo tensors
__device__ __align__(16) __nv_bfloat16 g_Yhi[16777216];
__device__ __align__(16) __nv_bfloat16 g_Ylo[16777216];
__device__ __align__(16) __nv_bfloat16 g_Zhi[16777216];
__device__ __align__(16) __nv_bfloat16 g_Zlo[16777216];
__device__ __align__(16) __nv_bfloat16 g_xbhi[16777216];
__device__ __align__(16) __nv_bfloat16 g_xblo[16777216];
// padded operand images [128][136]
__device__ __align__(16) __nv_bfloat16 g_Aophi[17408];
__device__ __align__(16) __nv_bfloat16 g_Aoplo[17408];
__device__ __align__(16) __nv_bfloat16 g_Wvophi[17408];
__device__ __align__(16) __nv_bfloat16 g_Wvoplo[17408];
__device__ __align__(16) __nv_bfloat16 g_athi[17408];   // attn hi [128][136]
__device__ __align__(16) __nv_bfloat16 g_atlo[17408];   // attn lo

// ---------------- helpers ----------------
__device__ __forceinline__ u32 smem_u32(const void* p) {
    u32 a; asm("{ .reg .u64 t; cvta.to.shared.u64 t, %1; cvt.u32.u64 %0, t; }" : "=r"(a) : "l"(p));
    return a;
}
__device__ __forceinline__ void cp16(u32 dst, const void* src) {
    asm volatile("cp.async.cg.shared.global [%0], [%1], 16;" :: "r"(dst), "l"(src));
}
__device__ __forceinline__ void cp_commit() { asm volatile("cp.async.commit_group;" ::: "memory"); }
template<int N> __device__ __forceinline__ void cp_wait() {
    asm volatile("cp.async.wait_group %0;" :: "n"(N) : "memory");
}

__device__ __forceinline__ void mma16816(float* c, const u32* a, const u32* b) {
    asm volatile("mma.sync.aligned.m16n8k16.row.col.f32.bf16.bf16.f32 "
        "{%0,%1,%2,%3}, {%4,%5,%6,%7}, {%8,%9}, {%0,%1,%2,%3};"
        : "+f"(c[0]), "+f"(c[1]), "+f"(c[2]), "+f"(c[3])
        : "r"(a[0]), "r"(a[1]), "r"(a[2]), "r"(a[3]), "r"(b[0]), "r"(b[1]));
}

__device__ __forceinline__ void pack_hilo(float a, float b, u32& hp, u32& lp) {
    __nv_bfloat16 ha = __float2bfloat16(a), hb = __float2bfloat16(b);
    float ra = a - __bfloat162float(ha), rb = b - __bfloat162float(hb);
    __nv_bfloat16 la = __float2bfloat16(ra), lb = __float2bfloat16(rb);
    hp = (u32)__bfloat16_as_ushort(ha) | ((u32)__bfloat16_as_ushort(hb) << 16);
    lp = (u32)__bfloat16_as_ushort(la) | ((u32)__bfloat16_as_ushort(lb) << 16);
}

// one product: C[128x128] += A[128xK] * B[128xK]^T, tiles padded to SW u32 words/row
template<int KC, int SW>
__device__ __forceinline__ void gemm_prod(float (&acc)[2][8][4], const u32* As, const u32* Bs,
                                          int wm, int wn, int g, int t) {
    #pragma unroll
    for (int kc = 0; kc < KC; kc++) {
        const int kw = kc * 8;
        u32 a[2][4];
        #pragma unroll
        for (int i = 0; i < 2; i++) {
            int rb = wm * 32 + i * 16;
            a[i][0] = As[(rb + g) * SW + kw + t];
            a[i][1] = As[(rb + g + 8) * SW + kw + t];
            a[i][2] = As[(rb + g) * SW + kw + t + 4];
            a[i][3] = As[(rb + g + 8) * SW + kw + t + 4];
        }
        u32 b[8][2];
        #pragma unroll
        for (int j = 0; j < 8; j++) {
            int rb = wn * 64 + j * 8;
            b[j][0] = Bs[(rb + g) * SW + kw + t];
            b[j][1] = Bs[(rb + g) * SW + kw + t + 4];
        }
        #pragma unroll
        for (int i = 0; i < 2; i++)
            #pragma unroll
            for (int j = 0; j < 8; j++)
                mma16816(acc[i][j], a[i], b[j]);
    }
}

// ---------------- K0: PE table ----------------
__global__ void k_init_pe() {
    int s = threadIdx.x;
    int p0 = s >> 5, p1 = s & 31;
    int j = p1 >> 1;
    float freq = powf(1000.0f, -(float)j * (1.0f / 64.0f));
    float arg = 3.14159265358979323846f * (float)p0 * freq;
    g_pe[s] = (p1 & 1) ? cosf(arg) : sinf(arg);
}

// ---------------- K1: A[d][e] + u[d], w[d] (merged reductions) ----------------
__global__ void k_prep(const float* __restrict__ W, const float* __restrict__ b) {
    __shared__ float wqd[128];
    __shared__ float wkd[128];
    __shared__ float red[128];
    int d = blockIdx.x, e = threadIdx.x;
    wqd[e] = W[384 * e + d];            // Wq[e,d]
    wkd[e] = W[384 * e + 128 + d];      // Wk[e,d]
    __syncthreads();
    float acc = 0.f;
    #pragma unroll 4
    for (int g = 0; g < 128; g++) acc += wqd[g] * W[384 * g + 128 + e];
    g_A[d * 128 + e] = acc;

    red[e] = wqd[e] * b[3 * e + 1];
    __syncthreads();
    #pragma unroll
    for (int st = 64; st > 0; st >>= 1) { if (e < st) red[e] += red[e + st]; __syncthreads(); }
    if (e == 0) g_u[d] = red[0];
    __syncthreads();
    red[e] = wkd[e] * b[3 * e];
    __syncthreads();
    #pragma unroll
    for (int st = 64; st > 0; st >>= 1) { if (e < st) red[e] += red[e + st]; __syncthreads(); }
    if (e == 0) g_w[d] = red[0];
}

// ---------------- K1b: padded bf16 operand images ----------------
__global__ void k_prepA(const float* __restrict__ W) {
    int e = blockIdx.x, d = threadIdx.x;
    float a = g_A[d * 128 + e];                 // Aop[e][d] = A[d][e]
    __nv_bfloat16 h = __float2bfloat16(a);
    __nv_bfloat16 l = __float2bfloat16(a - __bfloat162float(h));
    g_Aophi[e * 136 + d] = h;
    g_Aoplo[e * 136 + d] = l;
    float wv = W[384 * e + 256 + d];            // Wv[g=e][d]
    __nv_bfloat16 hw = __float2bfloat16(wv);
    __nv_bfloat16 lw = __float2bfloat16(wv - __bfloat162float(hw));
    g_Wvophi[e * 136 + d] = hw;
    g_Wvoplo[e * 136 + d] = lw;
}

// ---------------- K3: c partials + sum + alpha/beta/bv/gamma ----------------
__global__ void k_c(const float* __restrict__ x) {
    int n = blockIdx.x, ck = blockIdx.y, d = threadIdx.x;
    int s0 = ck * 128;
    const float* xp = x + ((size_t)n * 1024 + s0) * 128 + d;
    float a[8];
    #pragma unroll
    for (int q = 0; q < 8; q++) a[q] = 0.f;
    for (int s = 0; s < 128; s += 8) {
        #pragma unroll
        for (int q = 0; q < 8; q++)
            a[q] += g_pe[s0 + s + q] * xp[(size_t)(s + q) * 128];
    }
    g_cpart[ck * 16384 + n * 128 + d] =
        ((a[0] + a[1]) + (a[2] + a[3])) + ((a[4] + a[5]) + (a[6] + a[7]));
}
__global__ void k_csum() {
    int i = blockIdx.x * 256 + threadIdx.x;
    float s = 0.f;
    #pragma unroll
    for (int ck = 0; ck < 8; ck++) s += g_cpart[ck * 16384 + i];
    g_c[i] = s;
}
__global__ void k_ab(const float* __restrict__ b) {
    __shared__ float red[128];
    int n = threadIdx.x;
    float a = 0.f, bb = 0.f;
    #pragma unroll 4
    for (int d = 0; d < 128; d++) {
        float cv = g_c[n * 128 + d];
        a  += cv * g_u[d];
        bb += cv * g_w[d];
    }
    g_alpha[n] = a;
    g_beta[n]  = bb;
    g_bv[n] = b[3 * n + 2];
    red[n] = b[3 * n] * b[3 * n + 1];
    __syncthreads();
    #pragma unroll
    for (int st = 64; st > 0; st >>= 1) { if (n < st) red[n] += red[n + st]; __syncthreads(); }
    if (n == 0) g_gamma = 1024.0f * red[0];
}

// ---------------- K5: k_yz — Y = (pe X) Aop^T, Z = pe X  (mma.sync bf16) ----------------
__global__ void __launch_bounds__(256) k_yz(const float* __restrict__ X) {
    extern __shared__ __align__(16) unsigned char sm[];
    u32* Xhi = (u32*)sm;
    u32* Xlo = (u32*)(sm + 34816);
    u32* Ahi = (u32*)(sm + 69632);
    u32* Alo = (u32*)(sm + 104448);
    const int tid = threadIdx.x;
    const int rbase = blockIdx.x * 128;

    for (int i = tid; i < 2176; i += 256) {
        ((uint4*)Ahi)[i] = ((const uint4*)g_Aophi)[i];
        ((uint4*)Alo)[i] = ((const uint4*)g_Aoplo)[i];
    }
    #pragma unroll
    for (int i = 0; i < 16; i++) {
        int idx = tid + i * 256;
        int row = idx >> 5, jc = idx & 31;
        int r = rbase + row;
        float p = g_pe[r & 1023];
        float4 v = *(const float4*)(X + (size_t)r * 128 + jc * 4);
        u32 h0, l0, h1, l1;
        pack_hilo(v.x * p, v.y * p, h0, l0);
        pack_hilo(v.z * p, v.w * p, h1, l1);
        ((uint2*)Xhi)[row * 34 + jc] = make_uint2(h0, h1);
        ((uint2*)Xlo)[row * 34 + jc] = make_uint2(l0, l1);
        *(uint2*)(g_Zhi + (size_t)r * 128 + jc * 4) = make_uint2(h0, h1);
        *(uint2*)(g_Zlo + (size_t)r * 128 + jc * 4) = make_uint2(l0, l1);
    }
    __syncthreads();

    const int lane = tid & 31, warp = tid >> 5;
    const int wm = warp >> 1, wn = warp & 1, g = lane >> 2, t = lane & 3;
    float acc[2][8][4];
    #pragma unroll
    for (int i = 0; i < 2; i++)
        #pragma unroll
        for (int j = 0; j < 8; j++)
            #pragma unroll
            for (int q = 0; q < 4; q++) acc[i][j][q] = 0.f;

    gemm_prod<8, 68>(acc, Xhi, Ahi, wm, wn, g, t);
    gemm_prod<8, 68>(acc, Xhi, Alo, wm, wn, g, t);
    gemm_prod<8, 68>(acc, Xlo, Ahi, wm, wn, g, t);

    #pragma unroll
    for (int i = 0; i < 2; i++) {
        int r0 = rbase + wm * 32 + i * 16 + g;
        #pragma unroll
        for (int j = 0; j < 8; j++) {
            int e0 = wn * 64 + j * 8 + 2 * t;
            u32 h, l;
            pack_hilo(acc[i][j][0], acc[i][j][1], h, l);
            *(u32*)(g_Yhi + (size_t)r0 * 128 + e0) = h;
            *(u32*)(g_Ylo + (size_t)r0 * 128 + e0) = l;
            pack_hilo(acc[i][j][2], acc[i][j][3], h, l);
            *(u32*)(g_Yhi + (size_t)(r0 + 8) * 128 + e0) = h;
            *(u32*)(g_Ylo + (size_t)(r0 + 8) * 128 + e0) = l;
        }
    }
}

// ---------------- K6: k_sc — score partials = Y . Z^T (split-K, mma.sync) ----------------
__global__ void __launch_bounds__(256) k_sc() {
    extern __shared__ __align__(16) unsigned char sm[];
    u32 smb = smem_u32(sm);
    const int tid = threadIdx.x;

    const int lane = tid & 31, warp = tid >> 5;
    const int wm = warp >> 1, wn = warp & 1, g = lane >> 2, t = lane & 3;

    #define SC_ISSUE(it, buf) do {                                                   \
        size_t c0 = (size_t)blockIdx.x * 1024 + (size_t)(it) * 64;                   \
        for (int q = 0; q < 4; q++) {                                                \
            int idx = tid + q * 256;                                                 \
            int row = idx >> 3, jc = idx & 7;                                        \
            u32 d = smb + (buf) * 73728 + row * 144 + jc * 16;                       \
            size_t go = (size_t)row * 131072 + c0 + (size_t)jc * 8;                  \
            cp16(d,          g_Yhi + go);                                            \
            cp16(d + 18432,  g_Ylo + go);                                            \
            cp16(d + 36864,  g_Zhi + go);                                            \
            cp16(d + 55296,  g_Zlo + go);                                            \
        }                                                                            \
        cp_commit();                                                                 \
    } while (0)

    float acc[2][8][4];
    #pragma unroll
    for (int i = 0; i < 2; i++)
        #pragma unroll
        for (int j = 0; j < 8; j++)
            #pragma unroll
            for (int q = 0; q < 4; q++) acc[i][j][q] = 0.f;

    SC_ISSUE(0, 0);
    for (int it = 0; it < 16; it++) {
        if (it < 15) SC_ISSUE(it + 1, (it + 1) & 1);
        if (it < 15) cp_wait<1>(); else cp_wait<0>();
        __syncthreads();
        unsigned char* base = sm + (it & 1) * 73728;
        const u32* Yh = (const u32*)(base);
        const u32* Yl = (const u32*)(base + 18432);
        const u32* Zh = (const u32*)(base + 36864);
        const u32* Zl = (const u32*)(base + 55296);
        gemm_prod<4, 36>(acc, Yh, Zh, wm, wn, g, t);
        gemm_prod<4, 36>(acc, Yh, Zl, wm, wn, g, t);
        gemm_prod<4, 36>(acc, Yl, Zh, wm, wn, g, t);
        __syncthreads();
    }

    float* outp = g_spart + (size_t)blockIdx.x * 16384;
    #pragma unroll
    for (int i = 0; i < 2; i++) {
        int n0 = wm * 32 + i * 16 + g;
        #pragma unroll
        for (int j = 0; j < 8; j++) {
            int m0 = wn * 64 + j * 8 + 2 * t;
            *(float2*)(outp + n0 * 128 + m0)       = make_float2(acc[i][j][0], acc[i][j][1]);
            *(float2*)(outp + (n0 + 8) * 128 + m0) = make_float2(acc[i][j][2], acc[i][j][3]);
        }
    }
}

// ---------------- K7: reduce partials + alpha/beta/gamma ----------------
__global__ void k_reduce() {
    int f = blockIdx.x * 256 + threadIdx.x;   // grid 16
    float4 a0 = make_float4(0.f, 0.f, 0.f, 0.f), a1 = a0, a2 = a0, a3 = a0;
    for (int p = 0; p < 128; p += 4) {
        float4 v0 = *(const float4*)(g_spart + (size_t)(p + 0) * 16384 + 4 * f);
        float4 v1 = *(const float4*)(g_spart + (size_t)(p + 1) * 16384 + 4 * f);
        float4 v2 = *(const float4*)(g_spart + (size_t)(p + 2) * 16384 + 4 * f);
        float4 v3 = *(const float4*)(g_spart + (size_t)(p + 3) * 16384 + 4 * f);
        a0.x += v0.x; a0.y += v0.y; a0.z += v0.z; a0.w += v0.w;
        a1.x += v1.x; a1.y += v1.y; a1.z += v1.z; a1.w += v1.w;
        a2.x += v2.x; a2.y += v2.y; a2.z += v2.z; a2.w += v2.w;
        a3.x += v3.x; a3.y += v3.y; a3.z += v3.z; a3.w += v3.w;
    }
    float4 tot = make_float4((a0.x + a1.x) + (a2.x + a3.x), (a0.y + a1.y) + (a2.y + a3.y),
                             (a0.z + a1.z) + (a2.z + a3.z), (a0.w + a1.w) + (a2.w + a3.w));
    int n = f >> 5;
    int m0 = (4 * f) & 127;
    float al = g_alpha[n], gm = g_gamma;
    float4 be = *(const float4*)(g_beta + m0);
    *(float4*)(g_scores + 4 * f) = make_float4(tot.x + al + be.x + gm, tot.y + al + be.y + gm,
                                               tot.z + al + be.z + gm, tot.w + al + be.w + gm);
}

// ---------------- K8: softmax → attn hi/lo padded images [128][136] ----------------
__global__ void k_softmax() {
    int n = threadIdx.x;
    const float rs = 0.0883883476483184405f;
    const float* row = g_scores + n * 128;
    float mx = -1e30f;
    for (int j = 0; j < 128; j++) mx = fmaxf(mx, row[j]);
    float m = mx * rs;
    float sum = 0.f;
    for (int j = 0; j < 128; j++) sum += expf(row[j] * rs - m);
    float inv = 1.0f / sum;
    for (int j = 0; j < 128; j++) {
        float a = expf(row[j] * rs - m) * inv;
        __nv_bfloat16 h = __float2bfloat16(a);
        __nv_bfloat16 l = __float2bfloat16(a - __bfloat162float(h));
        g_athi[n * 136 + j] = h;
        g_atlo[n * 136 + j] = l;
    }
}

// ---------------- K9: xbarpe = attn @ Z (mma.sync + ldmatrix.trans B) ----------------
// grid 1024 (one s each), 256 thr. smem: attn hi/lo images + Z hi/lo tiles = 139264 B
__global__ void __launch_bounds__(256) k_xbar() {
    extern __shared__ __align__(16) unsigned char sm[];
    u32 smb = smem_u32(sm);
    const int tid = threadIdx.x;
    const int cb = blockIdx.x * 128;

    for (int i = tid; i < 2176; i += 256) {
        cp16(smb + i * 16,         ((const uint4*)g_athi) + i);
        cp16(smb + 34816 + i * 16, ((const uint4*)g_atlo) + i);
    }
    for (int i = tid; i < 2048; i += 256) {
        int row = i >> 4, jc = i & 15;
        u32 d = smb + 69632 + row * 272 + jc * 16;
        size_t go = (size_t)row * 131072 + cb + (size_t)jc * 8;
        cp16(d,         g_Zhi + go);
        cp16(d + 34816, g_Zlo + go);
    }
    cp_commit(); cp_wait<0>(); __syncthreads();

    const u32* Ahi = (const u32*)(sm);
    const u32* Alo = (const u32*)(sm + 34816);
    const int lane = tid & 31, warp = tid >> 5;
    const int wm = warp >> 1, wn = warp & 1, g = lane >> 2, t = lane & 3;

    float acc[2][8][4];
    #pragma unroll
    for (int i = 0; i < 2; i++)
        #pragma unroll
        for (int j = 0; j < 8; j++)
            #pragma unroll
            for (int q = 0; q < 4; q++) acc[i][j][q] = 0.f;

    const int krow_off = (lane & 7) + 8 * ((lane >> 3) & 1);
    const int ncol_off = 8 * (lane >> 4);

    #pragma unroll
    for (int kc = 0; kc < 8; kc++) {
        const int kw = kc * 8;
        u32 ah[2][4], al[2][4];
        #pragma unroll
        for (int i = 0; i < 2; i++) {
            int rb = wm * 32 + i * 16;
            ah[i][0] = Ahi[(rb + g) * 68 + kw + t];
            ah[i][1] = Ahi[(rb + g + 8) * 68 + kw + t];
            ah[i][2] = Ahi[(rb + g) * 68 + kw + t + 4];
            ah[i][3] = Ahi[(rb + g + 8) * 68 + kw + t + 4];
            al[i][0] = Alo[(rb + g) * 68 + kw + t];
            al[i][1] = Alo[(rb + g + 8) * 68 + kw + t];
            al[i][2] = Alo[(rb + g) * 68 + kw + t + 4];
            al[i][3] = Alo[(rb + g + 8) * 68 + kw + t + 4];
        }
        u32 zrow = smb + 69632 + (u32)(kc * 16 + krow_off) * 272;
        #pragma unroll
        for (int jp = 0; jp < 4; jp++) {
            u32 addr = zrow + (u32)(wn * 64 + jp * 16 + ncol_off) * 2;
            u32 bh[4], bl[4];
            asm volatile("ldmatrix.sync.aligned.m8n8.x4.trans.shared.b16 {%0,%1,%2,%3}, [%4];"
                : "=r"(bh[0]), "=r"(bh[1]), "=r"(bh[2]), "=r"(bh[3]) : "r"(addr));
            asm volatile("ldmatrix.sync.aligned.m8n8.x4.trans.shared.b16 {%0,%1,%2,%3}, [%4];"
                : "=r"(bl[0]), "=r"(bl[1]), "=r"(bl[2]), "=r"(bl[3]) : "r"(addr + 34816));
            #pragma unroll
            for (int i = 0; i < 2; i++) {
                mma16816(acc[i][2 * jp],     ah[i], bh);
                mma16816(acc[i][2 * jp + 1], ah[i], bh + 2);
                mma16816(acc[i][2 * jp],     al[i], bh);
                mma16816(acc[i][2 * jp + 1], al[i], bh + 2);
                mma16816(acc[i][2 * jp],     ah[i], bl);
                mma16816(acc[i][2 * jp + 1], ah[i], bl + 2);
            }
        }
    }

    #pragma unroll
    for (int i = 0; i < 2; i++) {
        int nr = wm * 32 + i * 16 + g;
        #pragma unroll
        for (int j = 0; j < 8; j++) {
            int col = cb + wn * 64 + j * 8 + 2 * t;
            u32 h, l;
            pack_hilo(acc[i][j][0], acc[i][j][1], h, l);
            *(u32*)(g_xbhi + (size_t)nr * 131072 + col) = h;
            *(u32*)(g_xblo + (size_t)nr * 131072 + col) = l;
            pack_hilo(acc[i][j][2], acc[i][j][3], h, l);
            *(u32*)(g_xbhi + (size_t)(nr + 8) * 131072 + col) = h;
            *(u32*)(g_xblo + (size_t)(nr + 8) * 131072 + col) = l;
        }
    }
}

// ---------------- K10: out = xbarpe @ Wv^T + bv (mma.sync) ----------------
__global__ void __launch_bounds__(256) k_out2(float* __restrict__ out) {
    extern __shared__ __align__(16) unsigned char sm[];
    u32 smb = smem_u32(sm);
    const int tid = threadIdx.x;
    const int rbase = blockIdx.x * 128;

    for (int i = tid; i < 2048; i += 256) {
        int row = i >> 4, jc = i & 15;
        u32 d = smb + row * 272 + jc * 16;
        size_t go = (size_t)(rbase + row) * 128 + (size_t)jc * 8;
        cp16(d,          g_xbhi + go);
        cp16(d + 34816,  g_xblo + go);
    }
    for (int i = tid; i < 2176; i += 256) {
        cp16(smb + 69632 + i * 16,  ((const uint4*)g_Wvophi) + i);
        cp16(smb + 104448 + i * 16, ((const uint4*)g_Wvoplo) + i);
    }
    cp_commit();
    cp_wait<0>();
    __syncthreads();

    const u32* Ahi = (const u32*)(sm);
    const u32* Alo = (const u32*)(sm + 34816);
    const u32* Bhi = (const u32*)(sm + 69632);
    const u32* Blo = (const u32*)(sm + 104448);

    const int lane = tid & 31, warp = tid >> 5;
    const int wm = warp >> 1, wn = warp & 1, g = lane >> 2, t = lane & 3;
    float acc[2][8][4];
    #pragma unroll
    for (int i = 0; i < 2; i++)
        #pragma unroll
        for (int j = 0; j < 8; j++)
            #pragma unroll
            for (int q = 0; q < 4; q++) acc[i][j][q] = 0.f;

    gemm_prod<8, 68>(acc, Ahi, Bhi, wm, wn, g, t);
    gemm_prod<8, 68>(acc, Ahi, Blo, wm, wn, g, t);
    gemm_prod<8, 68>(acc, Alo, Bhi, wm, wn, g, t);

    #pragma unroll
    for (int i = 0; i < 2; i++) {
        int r0 = rbase + wm * 32 + i * 16 + g;
        #pragma unroll
        for (int j = 0; j < 8; j++) {
            int e0 = wn * 64 + j * 8 + 2 * t;
            float2 bp = *(const float2*)(g_bv + e0);
            *(float2*)(out + (size_t)r0 * 128 + e0) =
                make_float2(acc[i][j][0] + bp.x, acc[i][j][1] + bp.y);
            *(float2*)(out + (size_t)(r0 + 8) * 128 + e0) =
                make_float2(acc[i][j][2] + bp.x, acc[i][j][3] + bp.y);
        }
    }
}

// ---------------- launch ----------------
extern "C" void kernel_launch(void* const* d_in, const int* in_sizes, int n_in,
                              void* d_out, int out_size) {
    const float* x = nullptr; const float* W = nullptr; const float* b = nullptr;
    for (int i = 0; i < n_in; i++) {
        if      (in_sizes[i] == 16777216) x = (const float*)d_in[i];
        else if (in_sizes[i] == 49152)    W = (const float*)d_in[i];
        else if (in_sizes[i] == 384)      b = (const float*)d_in[i];
    }
    if (!x) x = (const float*)d_in[0];
    if (!W) W = (const float*)d_in[1];
    if (!b) b = (const float*)d_in[2];
    float* out = (float*)d_out;

    cudaFuncSetAttribute(k_yz,   cudaFuncAttributeMaxDynamicSharedMemorySize, 139264);
    cudaFuncSetAttribute(k_sc,   cudaFuncAttributeMaxDynamicSharedMemorySize, 147456);
    cudaFuncSetAttribute(k_xbar, cudaFuncAttributeMaxDynamicSharedMemorySize, 139264);
    cudaFuncSetAttribute(k_out2, cudaFuncAttributeMaxDynamicSharedMemorySize, 139264);

    k_init_pe<<<1, 1024>>>();
    k_prep<<<128, 128>>>(W, b);
    k_prepA<<<128, 128>>>(W);
    k_c<<<dim3(128, 8), 128>>>(x);
    k_csum<<<64, 256>>>();
    k_ab<<<1, 128>>>(b);
    k_yz<<<1024, 256, 139264>>>(x);
    k_sc<<<128, 256, 147456>>>();
    k_reduce<<<16, 256>>>();
    k_softmax<<<1, 128>>>();
    k_xbar<<<1024, 256, 139264>>>();
    k_out2<<<1024, 256, 139264>>>(out);
}

// round 9
// speedup vs baseline: 2.2533x; 1.1705x over previous
#include <cuda_runtime.h>
#include <cuda_bf16.h>

typedef unsigned long long u64;
typedef unsigned int u32;

// ---------------- scratch ----------------
__device__ float g_spart[256 * 16384];
__device__ float g_scores[16384];
__device__ float g_pe[1024];
__device__ float g_A[16384];             // A[d][e] = sum_g Wq[g,d] Wk[g,e]
__device__ float g_bv[128];
__device__ float g_u[128];
__device__ float g_w[128];
__device__ float g_cpart[8 * 16384];
__device__ float g_c[16384];
__device__ float g_alpha[128];
__device__ float g_beta[128];
__device__ float g_gamma;

// bf16 hi/lo tensors
__device__ __align__(16) __nv_bfloat16 g_Yhi[16777216];
__device__ __align__(16) __nv_bfloat16 g_Ylo[16777216];
__device__ __align__(16) __nv_bfloat16 g_Zhi[16777216];
__device__ __align__(16) __nv_bfloat16 g_Zlo[16777216];
// padded operand images [128][136]
__device__ __align__(16) __nv_bfloat16 g_Aophi[17408];
__device__ __align__(16) __nv_bfloat16 g_Aoplo[17408];
__device__ __align__(16) __nv_bfloat16 g_Wvophi[17408];
__device__ __align__(16) __nv_bfloat16 g_Wvoplo[17408];
__device__ __align__(16) __nv_bfloat16 g_athi[17408];   // attn hi [128][136]
__device__ __align__(16) __nv_bfloat16 g_atlo[17408];   // attn lo

// ---------------- helpers ----------------
__device__ __forceinline__ u32 smem_u32(const void* p) {
    u32 a; asm("{ .reg .u64 t; cvta.to.shared.u64 t, %1; cvt.u32.u64 %0, t; }" : "=r"(a) : "l"(p));
    return a;
}
__device__ __forceinline__ void cp16(u32 dst, const void* src) {
    asm volatile("cp.async.cg.shared.global [%0], [%1], 16;" :: "r"(dst), "l"(src));
}
__device__ __forceinline__ void cp_commit() { asm volatile("cp.async.commit_group;" ::: "memory"); }
template<int N> __device__ __forceinline__ void cp_wait() {
    asm volatile("cp.async.wait_group %0;" :: "n"(N) : "memory");
}

__device__ __forceinline__ void mma16816(float* c, const u32* a, const u32* b) {
    asm volatile("mma.sync.aligned.m16n8k16.row.col.f32.bf16.bf16.f32 "
        "{%0,%1,%2,%3}, {%4,%5,%6,%7}, {%8,%9}, {%0,%1,%2,%3};"
        : "+f"(c[0]), "+f"(c[1]), "+f"(c[2]), "+f"(c[3])
        : "r"(a[0]), "r"(a[1]), "r"(a[2]), "r"(a[3]), "r"(b[0]), "r"(b[1]));
}

__device__ __forceinline__ void pack_hilo(float a, float b, u32& hp, u32& lp) {
    __nv_bfloat16 ha = __float2bfloat16(a), hb = __float2bfloat16(b);
    float ra = a - __bfloat162float(ha), rb = b - __bfloat162float(hb);
    __nv_bfloat16 la = __float2bfloat16(ra), lb = __float2bfloat16(rb);
    hp = (u32)__bfloat16_as_ushort(ha) | ((u32)__bfloat16_as_ushort(hb) << 16);
    lp = (u32)__bfloat16_as_ushort(la) | ((u32)__bfloat16_as_ushort(lb) << 16);
}

// one product: C[128x128] += A[128xK] * B[128xK]^T, tiles padded to SW u32 words/row
template<int KC, int SW>
__device__ __forceinline__ void gemm_prod(float (&acc)[2][8][4], const u32* As, const u32* Bs,
                                          int wm, int wn, int g, int t) {
    #pragma unroll
    for (int kc = 0; kc < KC; kc++) {
        const int kw = kc * 8;
        u32 a[2][4];
        #pragma unroll
        for (int i = 0; i < 2; i++) {
            int rb = wm * 32 + i * 16;
            a[i][0] = As[(rb + g) * SW + kw + t];
            a[i][1] = As[(rb + g + 8) * SW + kw + t];
            a[i][2] = As[(rb + g) * SW + kw + t + 4];
            a[i][3] = As[(rb + g + 8) * SW + kw + t + 4];
        }
        u32 b[8][2];
        #pragma unroll
        for (int j = 0; j < 8; j++) {
            int rb = wn * 64 + j * 8;
            b[j][0] = Bs[(rb + g) * SW + kw + t];
            b[j][1] = Bs[(rb + g) * SW + kw + t + 4];
        }
        #pragma unroll
        for (int i = 0; i < 2; i++)
            #pragma unroll
            for (int j = 0; j < 8; j++)
                mma16816(acc[i][j], a[i], b[j]);
    }
}

// ---------------- K0: PE table ----------------
__global__ void k_init_pe() {
    int s = threadIdx.x;
    int p0 = s >> 5, p1 = s & 31;
    int j = p1 >> 1;
    float freq = powf(1000.0f, -(float)j * (1.0f / 64.0f));
    float arg = 3.14159265358979323846f * (float)p0 * freq;
    g_pe[s] = (p1 & 1) ? cosf(arg) : sinf(arg);
}

// ---------------- K1: A[d][e] + u[d], w[d] ----------------
__global__ void k_prep(const float* __restrict__ W, const float* __restrict__ b) {
    __shared__ float wqd[128];
    __shared__ float wkd[128];
    __shared__ float red[128];
    int d = blockIdx.x, e = threadIdx.x;
    wqd[e] = W[384 * e + d];
    wkd[e] = W[384 * e + 128 + d];
    __syncthreads();
    float acc = 0.f;
    #pragma unroll 4
    for (int g = 0; g < 128; g++) acc += wqd[g] * W[384 * g + 128 + e];
    g_A[d * 128 + e] = acc;

    red[e] = wqd[e] * b[3 * e + 1];
    __syncthreads();
    #pragma unroll
    for (int st = 64; st > 0; st >>= 1) { if (e < st) red[e] += red[e + st]; __syncthreads(); }
    if (e == 0) g_u[d] = red[0];
    __syncthreads();
    red[e] = wkd[e] * b[3 * e];
    __syncthreads();
    #pragma unroll
    for (int st = 64; st > 0; st >>= 1) { if (e < st) red[e] += red[e + st]; __syncthreads(); }
    if (e == 0) g_w[d] = red[0];
}

// ---------------- K1b: padded bf16 operand images ----------------
__global__ void k_prepA(const float* __restrict__ W) {
    int e = blockIdx.x, d = threadIdx.x;
    float a = g_A[d * 128 + e];
    __nv_bfloat16 h = __float2bfloat16(a);
    __nv_bfloat16 l = __float2bfloat16(a - __bfloat162float(h));
    g_Aophi[e * 136 + d] = h;
    g_Aoplo[e * 136 + d] = l;
    float wv = W[384 * e + 256 + d];
    __nv_bfloat16 hw = __float2bfloat16(wv);
    __nv_bfloat16 lw = __float2bfloat16(wv - __bfloat162float(hw));
    g_Wvophi[e * 136 + d] = hw;
    g_Wvoplo[e * 136 + d] = lw;
}

__global__ void k_csum() {
    int i = blockIdx.x * 256 + threadIdx.x;
    float s = 0.f;
    #pragma unroll
    for (int ck = 0; ck < 8; ck++) s += g_cpart[ck * 16384 + i];
    g_c[i] = s;
}
__global__ void k_ab(const float* __restrict__ b) {
    __shared__ float red[128];
    int n = threadIdx.x;
    float a = 0.f, bb = 0.f;
    #pragma unroll 4
    for (int d = 0; d < 128; d++) {
        float cv = g_c[n * 128 + d];
        a  += cv * g_u[d];
        bb += cv * g_w[d];
    }
    g_alpha[n] = a;
    g_beta[n]  = bb;
    g_bv[n] = b[3 * n + 2];
    red[n] = b[3 * n] * b[3 * n + 1];
    __syncthreads();
    #pragma unroll
    for (int st = 64; st > 0; st >>= 1) { if (n < st) red[n] += red[n + st]; __syncthreads(); }
    if (n == 0) g_gamma = 1024.0f * red[0];
}

// ---------------- K5: k_yz — Y = (pe X) Aop^T, Z = pe X, + c-partials ----------------
// grid 1024, 256 thr. smem: Xhi Xlo Ahi Alo (4x34816) + redc (4096) = 143360 B
__global__ void __launch_bounds__(256) k_yz(const float* __restrict__ X) {
    extern __shared__ __align__(16) unsigned char sm[];
    u32* Xhi = (u32*)sm;
    u32* Xlo = (u32*)(sm + 34816);
    u32* Ahi = (u32*)(sm + 69632);
    u32* Alo = (u32*)(sm + 104448);
    float* redc = (float*)(sm + 139264);     // [8][128]
    const int tid = threadIdx.x;
    const int rbase = blockIdx.x * 128;

    for (int i = tid; i < 2176; i += 256) {
        ((uint4*)Ahi)[i] = ((const uint4*)g_Aophi)[i];
        ((uint4*)Alo)[i] = ((const uint4*)g_Aoplo)[i];
    }
    float csum[4] = {0.f, 0.f, 0.f, 0.f};
    #pragma unroll
    for (int i = 0; i < 16; i++) {
        int idx = tid + i * 256;
        int row = idx >> 5, jc = idx & 31;
        int r = rbase + row;
        float p = g_pe[r & 1023];
        float4 v = *(const float4*)(X + (size_t)r * 128 + jc * 4);
        float z0 = v.x * p, z1 = v.y * p, z2 = v.z * p, z3 = v.w * p;
        csum[0] += z0; csum[1] += z1; csum[2] += z2; csum[3] += z3;
        u32 h0, l0, h1, l1;
        pack_hilo(z0, z1, h0, l0);
        pack_hilo(z2, z3, h1, l1);
        ((uint2*)Xhi)[row * 34 + jc] = make_uint2(h0, h1);
        ((uint2*)Xlo)[row * 34 + jc] = make_uint2(l0, l1);
        *(uint2*)(g_Zhi + (size_t)r * 128 + jc * 4) = make_uint2(h0, h1);
        *(uint2*)(g_Zlo + (size_t)r * 128 + jc * 4) = make_uint2(l0, l1);
    }
    {
        int grp = tid >> 5, jc = tid & 31;
        *(float4*)(redc + grp * 128 + jc * 4) = make_float4(csum[0], csum[1], csum[2], csum[3]);
    }
    __syncthreads();
    if (tid < 128) {
        float t0 = (redc[0 * 128 + tid] + redc[1 * 128 + tid]) + (redc[2 * 128 + tid] + redc[3 * 128 + tid]);
        float t1 = (redc[4 * 128 + tid] + redc[5 * 128 + tid]) + (redc[6 * 128 + tid] + redc[7 * 128 + tid]);
        g_cpart[(blockIdx.x & 7) * 16384 + (blockIdx.x >> 3) * 128 + tid] = t0 + t1;
    }

    const int lane = tid & 31, warp = tid >> 5;
    const int wm = warp >> 1, wn = warp & 1, g = lane >> 2, t = lane & 3;
    float acc[2][8][4];
    #pragma unroll
    for (int i = 0; i < 2; i++)
        #pragma unroll
        for (int j = 0; j < 8; j++)
            #pragma unroll
            for (int q = 0; q < 4; q++) acc[i][j][q] = 0.f;

    gemm_prod<8, 68>(acc, Xhi, Ahi, wm, wn, g, t);
    gemm_prod<8, 68>(acc, Xhi, Alo, wm, wn, g, t);
    gemm_prod<8, 68>(acc, Xlo, Ahi, wm, wn, g, t);

    #pragma unroll
    for (int i = 0; i < 2; i++) {
        int r0 = rbase + wm * 32 + i * 16 + g;
        #pragma unroll
        for (int j = 0; j < 8; j++) {
            int e0 = wn * 64 + j * 8 + 2 * t;
            u32 h, l;
            pack_hilo(acc[i][j][0], acc[i][j][1], h, l);
            *(u32*)(g_Yhi + (size_t)r0 * 128 + e0) = h;
            *(u32*)(g_Ylo + (size_t)r0 * 128 + e0) = l;
            pack_hilo(acc[i][j][2], acc[i][j][3], h, l);
            *(u32*)(g_Yhi + (size_t)(r0 + 8) * 128 + e0) = h;
            *(u32*)(g_Ylo + (size_t)(r0 + 8) * 128 + e0) = l;
        }
    }
}

// ---------------- K6: k_sc — score partials = Y . Z^T (split-K 256, mma.sync) ----------------
__global__ void __launch_bounds__(256) k_sc() {
    extern __shared__ __align__(16) unsigned char sm[];
    u32 smb = smem_u32(sm);
    const int tid = threadIdx.x;

    const int lane = tid & 31, warp = tid >> 5;
    const int wm = warp >> 1, wn = warp & 1, g = lane >> 2, t = lane & 3;

    #define SC_ISSUE(it, buf) do {                                                   \
        size_t c0 = (size_t)blockIdx.x * 512 + (size_t)(it) * 64;                    \
        for (int q = 0; q < 4; q++) {                                                \
            int idx = tid + q * 256;                                                 \
            int row = idx >> 3, jc = idx & 7;                                        \
            u32 d = smb + (buf) * 73728 + row * 144 + jc * 16;                       \
            size_t go = (size_t)row * 131072 + c0 + (size_t)jc * 8;                  \
            cp16(d,          g_Yhi + go);                                            \
            cp16(d + 18432,  g_Ylo + go);                                            \
            cp16(d + 36864,  g_Zhi + go);                                            \
            cp16(d + 55296,  g_Zlo + go);                                            \
        }                                                                            \
        cp_commit();                                                                 \
    } while (0)

    float acc[2][8][4];
    #pragma unroll
    for (int i = 0; i < 2; i++)
        #pragma unroll
        for (int j = 0; j < 8; j++)
            #pragma unroll
            for (int q = 0; q < 4; q++) acc[i][j][q] = 0.f;

    SC_ISSUE(0, 0);
    for (int it = 0; it < 8; it++) {
        if (it < 7) SC_ISSUE(it + 1, (it + 1) & 1);
        if (it < 7) cp_wait<1>(); else cp_wait<0>();
        __syncthreads();
        unsigned char* base = sm + (it & 1) * 73728;
        const u32* Yh = (const u32*)(base);
        const u32* Yl = (const u32*)(base + 18432);
        const u32* Zh = (const u32*)(base + 36864);
        const u32* Zl = (const u32*)(base + 55296);
        gemm_prod<4, 36>(acc, Yh, Zh, wm, wn, g, t);
        gemm_prod<4, 36>(acc, Yh, Zl, wm, wn, g, t);
        gemm_prod<4, 36>(acc, Yl, Zh, wm, wn, g, t);
        __syncthreads();
    }

    float* outp = g_spart + (size_t)blockIdx.x * 16384;
    #pragma unroll
    for (int i = 0; i < 2; i++) {
        int n0 = wm * 32 + i * 16 + g;
        #pragma unroll
        for (int j = 0; j < 8; j++) {
            int m0 = wn * 64 + j * 8 + 2 * t;
            *(float2*)(outp + n0 * 128 + m0)       = make_float2(acc[i][j][0], acc[i][j][1]);
            *(float2*)(outp + (n0 + 8) * 128 + m0) = make_float2(acc[i][j][2], acc[i][j][3]);
        }
    }
}

// ---------------- K7: reduce 256 partials + alpha/beta/gamma ----------------
__global__ void k_reduce() {
    int f = blockIdx.x * 256 + threadIdx.x;   // grid 16
    float4 a0 = make_float4(0.f, 0.f, 0.f, 0.f), a1 = a0, a2 = a0, a3 = a0;
    for (int p = 0; p < 256; p += 4) {
        float4 v0 = *(const float4*)(g_spart + (size_t)(p + 0) * 16384 + 4 * f);
        float4 v1 = *(const float4*)(g_spart + (size_t)(p + 1) * 16384 + 4 * f);
        float4 v2 = *(const float4*)(g_spart + (size_t)(p + 2) * 16384 + 4 * f);
        float4 v3 = *(const float4*)(g_spart + (size_t)(p + 3) * 16384 + 4 * f);
        a0.x += v0.x; a0.y += v0.y; a0.z += v0.z; a0.w += v0.w;
        a1.x += v1.x; a1.y += v1.y; a1.z += v1.z; a1.w += v1.w;
        a2.x += v2.x; a2.y += v2.y; a2.z += v2.z; a2.w += v2.w;
        a3.x += v3.x; a3.y += v3.y; a3.z += v3.z; a3.w += v3.w;
    }
    float4 tot = make_float4((a0.x + a1.x) + (a2.x + a3.x), (a0.y + a1.y) + (a2.y + a3.y),
                             (a0.z + a1.z) + (a2.z + a3.z), (a0.w + a1.w) + (a2.w + a3.w));
    int n = f >> 5;
    int m0 = (4 * f) & 127;
    float al = g_alpha[n], gm = g_gamma;
    float4 be = *(const float4*)(g_beta + m0);
    *(float4*)(g_scores + 4 * f) = make_float4(tot.x + al + be.x + gm, tot.y + al + be.y + gm,
                                               tot.z + al + be.z + gm, tot.w + al + be.w + gm);
}

// ---------------- K8: parallel softmax → attn hi/lo images ----------------
__global__ void k_softmax() {
    __shared__ float red[128];
    int n = blockIdx.x, j = threadIdx.x;
    const float rs = 0.0883883476483184405f;
    float v = g_scores[n * 128 + j] * rs;
    red[j] = v;
    __syncthreads();
    #pragma unroll
    for (int st = 64; st > 0; st >>= 1) { if (j < st) red[j] = fmaxf(red[j], red[j + st]); __syncthreads(); }
    float m = red[0];
    __syncthreads();
    float e = expf(v - m);
    red[j] = e;
    __syncthreads();
    #pragma unroll
    for (int st = 64; st > 0; st >>= 1) { if (j < st) red[j] += red[j + st]; __syncthreads(); }
    float a = e / red[0];
    __nv_bfloat16 h = __float2bfloat16(a);
    __nv_bfloat16 l = __float2bfloat16(a - __bfloat162float(h));
    g_athi[n * 136 + j] = h;
    g_atlo[n * 136 + j] = l;
}

// ---------------- K9: k_xo — fused (attn @ Z) @ Wv^T + bv ----------------
// grid 1024 (one s each), 256 thr.
// smem: attn hi/lo (69632) | Z->interm hi/lo (69632) | Wv hi/lo (69632) = 208896 B
__global__ void __launch_bounds__(256) k_xo(float* __restrict__ out) {
    extern __shared__ __align__(16) unsigned char sm[];
    u32 smb = smem_u32(sm);
    const int tid = threadIdx.x;
    const int s_blk = blockIdx.x;
    const int cb = s_blk * 128;

    for (int i = tid; i < 2176; i += 256) {
        cp16(smb + i * 16,          ((const uint4*)g_athi) + i);
        cp16(smb + 34816 + i * 16,  ((const uint4*)g_atlo) + i);
        cp16(smb + 139264 + i * 16, ((const uint4*)g_Wvophi) + i);
        cp16(smb + 174080 + i * 16, ((const uint4*)g_Wvoplo) + i);
    }
    for (int i = tid; i < 2048; i += 256) {
        int row = i >> 4, jc = i & 15;
        u32 d = smb + 69632 + row * 272 + jc * 16;
        size_t go = (size_t)row * 131072 + cb + (size_t)jc * 8;
        cp16(d,         g_Zhi + go);
        cp16(d + 34816, g_Zlo + go);
    }
    cp_commit(); cp_wait<0>(); __syncthreads();

    const u32* Ahi = (const u32*)(sm);
    const u32* Alo = (const u32*)(sm + 34816);
    const int lane = tid & 31, warp = tid >> 5;
    const int wm = warp >> 1, wn = warp & 1, g = lane >> 2, t = lane & 3;

    float acc[2][8][4];
    #pragma unroll
    for (int i = 0; i < 2; i++)
        #pragma unroll
        for (int j = 0; j < 8; j++)
            #pragma unroll
            for (int q = 0; q < 4; q++) acc[i][j][q] = 0.f;

    const int krow_off = (lane & 7) + 8 * ((lane >> 3) & 1);
    const int ncol_off = 8 * (lane >> 4);

    // phase 1: interm = attn @ Z  (B via ldmatrix.trans)
    #pragma unroll
    for (int kc = 0; kc < 8; kc++) {
        const int kw = kc * 8;
        u32 ah[2][4], al[2][4];
        #pragma unroll
        for (int i = 0; i < 2; i++) {
            int rb = wm * 32 + i * 16;
            ah[i][0] = Ahi[(rb + g) * 68 + kw + t];
            ah[i][1] = Ahi[(rb + g + 8) * 68 + kw + t];
            ah[i][2] = Ahi[(rb + g) * 68 + kw + t + 4];
            ah[i][3] = Ahi[(rb + g + 8) * 68 + kw + t + 4];
            al[i][0] = Alo[(rb + g) * 68 + kw + t];
            al[i][1] = Alo[(rb + g + 8) * 68 + kw + t];
            al[i][2] = Alo[(rb + g) * 68 + kw + t + 4];
            al[i][3] = Alo[(rb + g + 8) * 68 + kw + t + 4];
        }
        u32 zrow = smb + 69632 + (u32)(kc * 16 + krow_off) * 272;
        #pragma unroll
        for (int jp = 0; jp < 4; jp++) {
            u32 addr = zrow + (u32)(wn * 64 + jp * 16 + ncol_off) * 2;
            u32 bh[4], bl[4];
            asm volatile("ldmatrix.sync.aligned.m8n8.x4.trans.shared.b16 {%0,%1,%2,%3}, [%4];"
                : "=r"(bh[0]), "=r"(bh[1]), "=r"(bh[2]), "=r"(bh[3]) : "r"(addr));
            asm volatile("ldmatrix.sync.aligned.m8n8.x4.trans.shared.b16 {%0,%1,%2,%3}, [%4];"
                : "=r"(bl[0]), "=r"(bl[1]), "=r"(bl[2]), "=r"(bl[3]) : "r"(addr + 34816));
            #pragma unroll
            for (int i = 0; i < 2; i++) {
                mma16816(acc[i][2 * jp],     ah[i], bh);
                mma16816(acc[i][2 * jp + 1], ah[i], bh + 2);
                mma16816(acc[i][2 * jp],     al[i], bh);
                mma16816(acc[i][2 * jp + 1], al[i], bh + 2);
                mma16816(acc[i][2 * jp],     ah[i], bl);
                mma16816(acc[i][2 * jp + 1], ah[i], bl + 2);
            }
        }
    }

    // repack interm into the Z region as hi/lo [n][136]
    __syncthreads();
    #pragma unroll
    for (int i = 0; i < 2; i++) {
        int nr = wm * 32 + i * 16 + g;
        #pragma unroll
        for (int j = 0; j < 8; j++) {
            int col = wn * 64 + j * 8 + 2 * t;
            u32 h, l;
            pack_hilo(acc[i][j][0], acc[i][j][1], h, l);
            *(u32*)(sm + 69632 + (u32)nr * 272 + col * 2) = h;
            *(u32*)(sm + 104448 + (u32)nr * 272 + col * 2) = l;
            pack_hilo(acc[i][j][2], acc[i][j][3], h, l);
            *(u32*)(sm + 69632 + (u32)(nr + 8) * 272 + col * 2) = h;
            *(u32*)(sm + 104448 + (u32)(nr + 8) * 272 + col * 2) = l;
        }
    }
    __syncthreads();

    // phase 2: out = interm @ Wv^T + bv
    #pragma unroll
    for (int i = 0; i < 2; i++)
        #pragma unroll
        for (int j = 0; j < 8; j++)
            #pragma unroll
            for (int q = 0; q < 4; q++) acc[i][j][q] = 0.f;

    const u32* Ih = (const u32*)(sm + 69632);
    const u32* Il = (const u32*)(sm + 104448);
    const u32* Wh = (const u32*)(sm + 139264);
    const u32* Wl = (const u32*)(sm + 174080);
    gemm_prod<8, 68>(acc, Ih, Wh, wm, wn, g, t);
    gemm_prod<8, 68>(acc, Ih, Wl, wm, wn, g, t);
    gemm_prod<8, 68>(acc, Il, Wh, wm, wn, g, t);

    #pragma unroll
    for (int i = 0; i < 2; i++) {
        int n0 = wm * 32 + i * 16 + g;
        size_t r0 = (size_t)n0 * 1024 + s_blk;
        size_t r1 = (size_t)(n0 + 8) * 1024 + s_blk;
        #pragma unroll
        for (int j = 0; j < 8; j++) {
            int e0 = wn * 64 + j * 8 + 2 * t;
            float2 bp = *(const float2*)(g_bv + e0);
            *(float2*)(out + r0 * 128 + e0) =
                make_float2(acc[i][j][0] + bp.x, acc[i][j][1] + bp.y);
            *(float2*)(out + r1 * 128 + e0) =
                make_float2(acc[i][j][2] + bp.x, acc[i][j][3] + bp.y);
        }
    }
}

// ---------------- launch ----------------
extern "C" void kernel_launch(void* const* d_in, const int* in_sizes, int n_in,
                              void* d_out, int out_size) {
    const float* x = nullptr; const float* W = nullptr; const float* b = nullptr;
    for (int i = 0; i < n_in; i++) {
        if      (in_sizes[i] == 16777216) x = (const float*)d_in[i];
        else if (in_sizes[i] == 49152)    W = (const float*)d_in[i];
        else if (in_sizes[i] == 384)      b = (const float*)d_in[i];
    }
    if (!x) x = (const float*)d_in[0];
    if (!W) W = (const float*)d_in[1];
    if (!b) b = (const float*)d_in[2];
    float* out = (float*)d_out;

    cudaFuncSetAttribute(k_yz, cudaFuncAttributeMaxDynamicSharedMemorySize, 143360);
    cudaFuncSetAttribute(k_sc, cudaFuncAttributeMaxDynamicSharedMemorySize, 147456);
    cudaFuncSetAttribute(k_xo, cudaFuncAttributeMaxDynamicSharedMemorySize, 208896);

    k_init_pe<<<1, 1024>>>();
    k_prep<<<128, 128>>>(W, b);
    k_prepA<<<128, 128>>>(W);
    k_yz<<<1024, 256, 143360>>>(x);
    k_csum<<<64, 256>>>();
    k_ab<<<1, 128>>>(b);
    k_sc<<<256, 256, 147456>>>();
    k_reduce<<<16, 256>>>();
    k_softmax<<<128, 128>>>();
    k_xo<<<1024, 256, 208896>>>(out);
}

// round 10
// speedup vs baseline: 2.5478x; 1.1307x over previous
#include <cuda_runtime.h>
#include <cuda_bf16.h>

typedef unsigned long long u64;
typedef unsigned int u32;

// ---------------- scratch ----------------
__device__ float g_spart[256 * 16384];
__device__ float g_scores[16384];
__device__ float g_pe[1024];
__device__ float g_A[16384];             // A[d][e] = sum_g Wq[g,d] Wk[g,e]
__device__ float g_bv[128];
__device__ float g_u[128];
__device__ float g_w[128];
__device__ float g_cpart[16 * 16384];
__device__ float g_c[16384];
__device__ float g_alpha[128];
__device__ float g_beta[128];
__device__ float g_gamma;

// bf16 hi/lo tensors
__device__ __align__(16) __nv_bfloat16 g_Yhi[16777216];
__device__ __align__(16) __nv_bfloat16 g_Ylo[16777216];
__device__ __align__(16) __nv_bfloat16 g_Zhi[16777216];
__device__ __align__(16) __nv_bfloat16 g_Zlo[16777216];
// padded operand images [128][136]
__device__ __align__(16) __nv_bfloat16 g_Aophi[17408];
__device__ __align__(16) __nv_bfloat16 g_Aoplo[17408];
__device__ __align__(16) __nv_bfloat16 g_Wvophi[17408];
__device__ __align__(16) __nv_bfloat16 g_Wvoplo[17408];
__device__ __align__(16) __nv_bfloat16 g_athi[17408];   // attn hi [128][136]
__device__ __align__(16) __nv_bfloat16 g_atlo[17408];   // attn lo

// ---------------- helpers ----------------
__device__ __forceinline__ u32 smem_u32(const void* p) {
    u32 a; asm("{ .reg .u64 t; cvta.to.shared.u64 t, %1; cvt.u32.u64 %0, t; }" : "=r"(a) : "l"(p));
    return a;
}
__device__ __forceinline__ void cp16(u32 dst, const void* src) {
    asm volatile("cp.async.cg.shared.global [%0], [%1], 16;" :: "r"(dst), "l"(src));
}
__device__ __forceinline__ void cp_commit() { asm volatile("cp.async.commit_group;" ::: "memory"); }
template<int N> __device__ __forceinline__ void cp_wait() {
    asm volatile("cp.async.wait_group %0;" :: "n"(N) : "memory");
}

__device__ __forceinline__ void mma16816(float* c, const u32* a, const u32* b) {
    asm volatile("mma.sync.aligned.m16n8k16.row.col.f32.bf16.bf16.f32 "
        "{%0,%1,%2,%3}, {%4,%5,%6,%7}, {%8,%9}, {%0,%1,%2,%3};"
        : "+f"(c[0]), "+f"(c[1]), "+f"(c[2]), "+f"(c[3])
        : "r"(a[0]), "r"(a[1]), "r"(a[2]), "r"(a[3]), "r"(b[0]), "r"(b[1]));
}

__device__ __forceinline__ void pack_hilo(float a, float b, u32& hp, u32& lp) {
    __nv_bfloat16 ha = __float2bfloat16(a), hb = __float2bfloat16(b);
    float ra = a - __bfloat162float(ha), rb = b - __bfloat162float(hb);
    __nv_bfloat16 la = __float2bfloat16(ra), lb = __float2bfloat16(rb);
    hp = (u32)__bfloat16_as_ushort(ha) | ((u32)__bfloat16_as_ushort(hb) << 16);
    lp = (u32)__bfloat16_as_ushort(la) | ((u32)__bfloat16_as_ushort(lb) << 16);
}

// one product: C[128x128] += A[128xK] * B[128xK]^T, tiles padded to SW u32 words/row
template<int KC, int SW>
__device__ __forceinline__ void gemm_prod(float (&acc)[2][8][4], const u32* As, const u32* Bs,
                                          int wm, int wn, int g, int t) {
    #pragma unroll
    for (int kc = 0; kc < KC; kc++) {
        const int kw = kc * 8;
        u32 a[2][4];
        #pragma unroll
        for (int i = 0; i < 2; i++) {
            int rb = wm * 32 + i * 16;
            a[i][0] = As[(rb + g) * SW + kw + t];
            a[i][1] = As[(rb + g + 8) * SW + kw + t];
            a[i][2] = As[(rb + g) * SW + kw + t + 4];
            a[i][3] = As[(rb + g + 8) * SW + kw + t + 4];
        }
        u32 b[8][2];
        #pragma unroll
        for (int j = 0; j < 8; j++) {
            int rb = wn * 64 + j * 8;
            b[j][0] = Bs[(rb + g) * SW + kw + t];
            b[j][1] = Bs[(rb + g) * SW + kw + t + 4];
        }
        #pragma unroll
        for (int i = 0; i < 2; i++)
            #pragma unroll
            for (int j = 0; j < 8; j++)
                mma16816(acc[i][j], a[i], b[j]);
    }
}

// yz product via ldmatrix: acc[8][4] covers m16 (wm) x n128 (wn half, 8 tiles)
__device__ __forceinline__ void yz_prod(float (&acc)[8][4], u32 xb, u32 ab,
                                        int wm, int wn, int lane) {
    const int q = lane >> 3, r = lane & 7;
    #pragma unroll
    for (int kc = 0; kc < 8; kc++) {
        u32 a[4];
        u32 addrA = xb + (u32)((wm * 16 + r + (q & 1) * 8) * 136 + kc * 16 + (q >> 1) * 8) * 2;
        asm volatile("ldmatrix.sync.aligned.m8n8.x4.shared.b16 {%0,%1,%2,%3}, [%4];"
            : "=r"(a[0]), "=r"(a[1]), "=r"(a[2]), "=r"(a[3]) : "r"(addrA));
        #pragma unroll
        for (int jp = 0; jp < 4; jp++) {
            u32 b[4];
            u32 addrB = ab + (u32)((wn * 64 + jp * 16 + r + (q >> 1) * 8) * 136 + kc * 16 + (q & 1) * 8) * 2;
            asm volatile("ldmatrix.sync.aligned.m8n8.x4.shared.b16 {%0,%1,%2,%3}, [%4];"
                : "=r"(b[0]), "=r"(b[1]), "=r"(b[2]), "=r"(b[3]) : "r"(addrB));
            mma16816(acc[2 * jp],     a, b);
            mma16816(acc[2 * jp + 1], a, b + 2);
        }
    }
}

// ---------------- K0: PE table ----------------
__global__ void k_init_pe() {
    int s = threadIdx.x;
    int p0 = s >> 5, p1 = s & 31;
    int j = p1 >> 1;
    float freq = powf(1000.0f, -(float)j * (1.0f / 64.0f));
    float arg = 3.14159265358979323846f * (float)p0 * freq;
    g_pe[s] = (p1 & 1) ? cosf(arg) : sinf(arg);
}

// ---------------- K1: A[d][e] + u[d], w[d] ----------------
__global__ void k_prep(const float* __restrict__ W, const float* __restrict__ b) {
    __shared__ float wqd[128];
    __shared__ float wkd[128];
    __shared__ float red[128];
    int d = blockIdx.x, e = threadIdx.x;
    wqd[e] = W[384 * e + d];
    wkd[e] = W[384 * e + 128 + d];
    __syncthreads();
    float acc = 0.f;
    #pragma unroll 4
    for (int g = 0; g < 128; g++) acc += wqd[g] * W[384 * g + 128 + e];
    g_A[d * 128 + e] = acc;

    red[e] = wqd[e] * b[3 * e + 1];
    __syncthreads();
    #pragma unroll
    for (int st = 64; st > 0; st >>= 1) { if (e < st) red[e] += red[e + st]; __syncthreads(); }
    if (e == 0) g_u[d] = red[0];
    __syncthreads();
    red[e] = wkd[e] * b[3 * e];
    __syncthreads();
    #pragma unroll
    for (int st = 64; st > 0; st >>= 1) { if (e < st) red[e] += red[e + st]; __syncthreads(); }
    if (e == 0) g_w[d] = red[0];
}

// ---------------- K1b: padded bf16 operand images ----------------
__global__ void k_prepA(const float* __restrict__ W) {
    int e = blockIdx.x, d = threadIdx.x;
    float a = g_A[d * 128 + e];
    __nv_bfloat16 h = __float2bfloat16(a);
    __nv_bfloat16 l = __float2bfloat16(a - __bfloat162float(h));
    g_Aophi[e * 136 + d] = h;
    g_Aoplo[e * 136 + d] = l;
    float wv = W[384 * e + 256 + d];
    __nv_bfloat16 hw = __float2bfloat16(wv);
    __nv_bfloat16 lw = __float2bfloat16(wv - __bfloat162float(hw));
    g_Wvophi[e * 136 + d] = hw;
    g_Wvoplo[e * 136 + d] = lw;
}

__global__ void k_csum() {
    int i = blockIdx.x * 256 + threadIdx.x;
    float s = 0.f;
    #pragma unroll
    for (int ck = 0; ck < 16; ck++) s += g_cpart[ck * 16384 + i];
    g_c[i] = s;
}
__global__ void k_ab(const float* __restrict__ b) {
    __shared__ float red[128];
    int n = threadIdx.x;
    float a = 0.f, bb = 0.f;
    #pragma unroll 4
    for (int d = 0; d < 128; d++) {
        float cv = g_c[n * 128 + d];
        a  += cv * g_u[d];
        bb += cv * g_w[d];
    }
    g_alpha[n] = a;
    g_beta[n]  = bb;
    g_bv[n] = b[3 * n + 2];
    red[n] = b[3 * n] * b[3 * n + 1];
    __syncthreads();
    #pragma unroll
    for (int st = 64; st > 0; st >>= 1) { if (n < st) red[n] += red[n + st]; __syncthreads(); }
    if (n == 0) g_gamma = 1024.0f * red[0];
}

// ---------------- K5: k_yz — Y = (pe X) Aop^T, Z = pe X, + c-partials ----------------
// grid 2048 (64 rows each), 256 thr, 2 blocks/SM.
// smem: Xhi[64][136] @0 (17408) | Xlo @17408 | Ahi[128][136] @34816 | Alo @69632 | redc @104448 (4096)
__global__ void __launch_bounds__(256, 2) k_yz(const float* __restrict__ X) {
    extern __shared__ __align__(16) unsigned char sm[];
    u32 smb = smem_u32(sm);
    float* redc = (float*)(sm + 104448);
    const int tid = threadIdx.x;
    const int rbase = blockIdx.x * 64;

    for (int i = tid; i < 2176; i += 256) {
        cp16(smb + 34816 + i * 16, ((const uint4*)g_Aophi) + i);
        cp16(smb + 69632 + i * 16, ((const uint4*)g_Aoplo) + i);
    }
    cp_commit();

    float csum[4] = {0.f, 0.f, 0.f, 0.f};
    #pragma unroll
    for (int i = 0; i < 8; i++) {
        int idx = tid + i * 256;
        int row = idx >> 5, jc = idx & 31;
        int r = rbase + row;
        float p = g_pe[r & 1023];
        float4 v = *(const float4*)(X + (size_t)r * 128 + jc * 4);
        float z0 = v.x * p, z1 = v.y * p, z2 = v.z * p, z3 = v.w * p;
        csum[0] += z0; csum[1] += z1; csum[2] += z2; csum[3] += z3;
        u32 h0, l0, h1, l1;
        pack_hilo(z0, z1, h0, l0);
        pack_hilo(z2, z3, h1, l1);
        *(uint2*)(sm + (u32)(row * 272 + jc * 8))         = make_uint2(h0, h1);
        *(uint2*)(sm + 17408 + (u32)(row * 272 + jc * 8)) = make_uint2(l0, l1);
        *(uint2*)(g_Zhi + (size_t)r * 128 + jc * 4) = make_uint2(h0, h1);
        *(uint2*)(g_Zlo + (size_t)r * 128 + jc * 4) = make_uint2(l0, l1);
    }
    {
        int grp = tid >> 5, jc = tid & 31;
        *(float4*)(redc + grp * 128 + jc * 4) = make_float4(csum[0], csum[1], csum[2], csum[3]);
    }
    cp_wait<0>();
    __syncthreads();
    if (tid < 128) {
        float t0 = (redc[0 * 128 + tid] + redc[1 * 128 + tid]) + (redc[2 * 128 + tid] + redc[3 * 128 + tid]);
        float t1 = (redc[4 * 128 + tid] + redc[5 * 128 + tid]) + (redc[6 * 128 + tid] + redc[7 * 128 + tid]);
        g_cpart[(blockIdx.x & 15) * 16384 + (blockIdx.x >> 4) * 128 + tid] = t0 + t1;
    }

    const int lane = tid & 31, warp = tid >> 5;
    const int wm = warp >> 1, wn = warp & 1, g = lane >> 2, t = lane & 3;
    float acc[8][4];
    #pragma unroll
    for (int j = 0; j < 8; j++)
        #pragma unroll
        for (int q = 0; q < 4; q++) acc[j][q] = 0.f;

    yz_prod(acc, smb,         smb + 34816, wm, wn, lane);   // Xhi * Ahi
    yz_prod(acc, smb,         smb + 69632, wm, wn, lane);   // Xhi * Alo
    yz_prod(acc, smb + 17408, smb + 34816, wm, wn, lane);   // Xlo * Ahi

    {
        int r0 = rbase + wm * 16 + g;
        #pragma unroll
        for (int j = 0; j < 8; j++) {
            int e0 = wn * 64 + (j >> 1) * 16 + (j & 1) * 8 + 2 * t;
            u32 h, l;
            pack_hilo(acc[j][0], acc[j][1], h, l);
            *(u32*)(g_Yhi + (size_t)r0 * 128 + e0) = h;
            *(u32*)(g_Ylo + (size_t)r0 * 128 + e0) = l;
            pack_hilo(acc[j][2], acc[j][3], h, l);
            *(u32*)(g_Yhi + (size_t)(r0 + 8) * 128 + e0) = h;
            *(u32*)(g_Ylo + (size_t)(r0 + 8) * 128 + e0) = l;
        }
    }
}

// ---------------- K6: k_sc — score partials = Y . Z^T (split-K 256, mma.sync) ----------------
__global__ void __launch_bounds__(256) k_sc() {
    extern __shared__ __align__(16) unsigned char sm[];
    u32 smb = smem_u32(sm);
    const int tid = threadIdx.x;

    const int lane = tid & 31, warp = tid >> 5;
    const int wm = warp >> 1, wn = warp & 1, g = lane >> 2, t = lane & 3;

    #define SC_ISSUE(it, buf) do {                                                   \
        size_t c0 = (size_t)blockIdx.x * 512 + (size_t)(it) * 64;                    \
        for (int q = 0; q < 4; q++) {                                                \
            int idx = tid + q * 256;                                                 \
            int row = idx >> 3, jc = idx & 7;                                        \
            u32 d = smb + (buf) * 73728 + row * 144 + jc * 16;                       \
            size_t go = (size_t)row * 131072 + c0 + (size_t)jc * 8;                  \
            cp16(d,          g_Yhi + go);                                            \
            cp16(d + 18432,  g_Ylo + go);                                            \
            cp16(d + 36864,  g_Zhi + go);                                            \
            cp16(d + 55296,  g_Zlo + go);                                            \
        }                                                                            \
        cp_commit();                                                                 \
    } while (0)

    float acc[2][8][4];
    #pragma unroll
    for (int i = 0; i < 2; i++)
        #pragma unroll
        for (int j = 0; j < 8; j++)
            #pragma unroll
            for (int q = 0; q < 4; q++) acc[i][j][q] = 0.f;

    SC_ISSUE(0, 0);
    for (int it = 0; it < 8; it++) {
        if (it < 7) SC_ISSUE(it + 1, (it + 1) & 1);
        if (it < 7) cp_wait<1>(); else cp_wait<0>();
        __syncthreads();
        unsigned char* base = sm + (it & 1) * 73728;
        const u32* Yh = (const u32*)(base);
        const u32* Yl = (const u32*)(base + 18432);
        const u32* Zh = (const u32*)(base + 36864);
        const u32* Zl = (const u32*)(base + 55296);
        gemm_prod<4, 36>(acc, Yh, Zh, wm, wn, g, t);
        gemm_prod<4, 36>(acc, Yh, Zl, wm, wn, g, t);
        gemm_prod<4, 36>(acc, Yl, Zh, wm, wn, g, t);
        __syncthreads();
    }

    float* outp = g_spart + (size_t)blockIdx.x * 16384;
    #pragma unroll
    for (int i = 0; i < 2; i++) {
        int n0 = wm * 32 + i * 16 + g;
        #pragma unroll
        for (int j = 0; j < 8; j++) {
            int m0 = wn * 64 + j * 8 + 2 * t;
            *(float2*)(outp + n0 * 128 + m0)       = make_float2(acc[i][j][0], acc[i][j][1]);
            *(float2*)(outp + (n0 + 8) * 128 + m0) = make_float2(acc[i][j][2], acc[i][j][3]);
        }
    }
}

// ---------------- K7: reduce 256 partials + alpha/beta/gamma ----------------
__global__ void k_reduce() {
    int f = blockIdx.x * 256 + threadIdx.x;   // grid 16
    float4 a0 = make_float4(0.f, 0.f, 0.f, 0.f), a1 = a0, a2 = a0, a3 = a0;
    for (int p = 0; p < 256; p += 4) {
        float4 v0 = *(const float4*)(g_spart + (size_t)(p + 0) * 16384 + 4 * f);
        float4 v1 = *(const float4*)(g_spart + (size_t)(p + 1) * 16384 + 4 * f);
        float4 v2 = *(const float4*)(g_spart + (size_t)(p + 2) * 16384 + 4 * f);
        float4 v3 = *(const float4*)(g_spart + (size_t)(p + 3) * 16384 + 4 * f);
        a0.x += v0.x; a0.y += v0.y; a0.z += v0.z; a0.w += v0.w;
        a1.x += v1.x; a1.y += v1.y; a1.z += v1.z; a1.w += v1.w;
        a2.x += v2.x; a2.y += v2.y; a2.z += v2.z; a2.w += v2.w;
        a3.x += v3.x; a3.y += v3.y; a3.z += v3.z; a3.w += v3.w;
    }
    float4 tot = make_float4((a0.x + a1.x) + (a2.x + a3.x), (a0.y + a1.y) + (a2.y + a3.y),
                             (a0.z + a1.z) + (a2.z + a3.z), (a0.w + a1.w) + (a2.w + a3.w));
    int n = f >> 5;
    int m0 = (4 * f) & 127;
    float al = g_alpha[n], gm = g_gamma;
    float4 be = *(const float4*)(g_beta + m0);
    *(float4*)(g_scores + 4 * f) = make_float4(tot.x + al + be.x + gm, tot.y + al + be.y + gm,
                                               tot.z + al + be.z + gm, tot.w + al + be.w + gm);
}

// ---------------- K8: parallel softmax → attn hi/lo images ----------------
__global__ void k_softmax() {
    __shared__ float red[128];
    int n = blockIdx.x, j = threadIdx.x;
    const float rs = 0.0883883476483184405f;
    float v = g_scores[n * 128 + j] * rs;
    red[j] = v;
    __syncthreads();
    #pragma unroll
    for (int st = 64; st > 0; st >>= 1) { if (j < st) red[j] = fmaxf(red[j], red[j + st]); __syncthreads(); }
    float m = red[0];
    __syncthreads();
    float e = expf(v - m);
    red[j] = e;
    __syncthreads();
    #pragma unroll
    for (int st = 64; st > 0; st >>= 1) { if (j < st) red[j] += red[j + st]; __syncthreads(); }
    float a = e / red[0];
    __nv_bfloat16 h = __float2bfloat16(a);
    __nv_bfloat16 l = __float2bfloat16(a - __bfloat162float(h));
    g_athi[n * 136 + j] = h;
    g_atlo[n * 136 + j] = l;
}

// ---------------- K9: k_xo — fused (attn @ Z) @ Wv^T + bv ----------------
// grid 1024 (one s each), 256 thr.
// smem: attn hi/lo (69632) | Z->interm hi/lo (69632) | Wv hi/lo (69632) = 208896 B
__global__ void __launch_bounds__(256) k_xo(float* __restrict__ out) {
    extern __shared__ __align__(16) unsigned char sm[];
    u32 smb = smem_u32(sm);
    const int tid = threadIdx.x;
    const int s_blk = blockIdx.x;
    const int cb = s_blk * 128;

    for (int i = tid; i < 2176; i += 256) {
        cp16(smb + i * 16,          ((const uint4*)g_athi) + i);
        cp16(smb + 34816 + i * 16,  ((const uint4*)g_atlo) + i);
        cp16(smb + 139264 + i * 16, ((const uint4*)g_Wvophi) + i);
        cp16(smb + 174080 + i * 16, ((const uint4*)g_Wvoplo) + i);
    }
    for (int i = tid; i < 2048; i += 256) {
        int row = i >> 4, jc = i & 15;
        u32 d = smb + 69632 + row * 272 + jc * 16;
        size_t go = (size_t)row * 131072 + cb + (size_t)jc * 8;
        cp16(d,         g_Zhi + go);
        cp16(d + 34816, g_Zlo + go);
    }
    cp_commit(); cp_wait<0>(); __syncthreads();

    const u32* Ahi = (const u32*)(sm);
    const u32* Alo = (const u32*)(sm + 34816);
    const int lane = tid & 31, warp = tid >> 5;
    const int wm = warp >> 1, wn = warp & 1, g = lane >> 2, t = lane & 3;

    float acc[2][8][4];
    #pragma unroll
    for (int i = 0; i < 2; i++)
        #pragma unroll
        for (int j = 0; j < 8; j++)
            #pragma unroll
            for (int q = 0; q < 4; q++) acc[i][j][q] = 0.f;

    const int krow_off = (lane & 7) + 8 * ((lane >> 3) & 1);
    const int ncol_off = 8 * (lane >> 4);

    // phase 1: interm = attn @ Z  (B via ldmatrix.trans)
    #pragma unroll
    for (int kc = 0; kc < 8; kc++) {
        const int kw = kc * 8;
        u32 ah[2][4], al[2][4];
        #pragma unroll
        for (int i = 0; i < 2; i++) {
            int rb = wm * 32 + i * 16;
            ah[i][0] = Ahi[(rb + g) * 68 + kw + t];
            ah[i][1] = Ahi[(rb + g + 8) * 68 + kw + t];
            ah[i][2] = Ahi[(rb + g) * 68 + kw + t + 4];
            ah[i][3] = Ahi[(rb + g + 8) * 68 + kw + t + 4];
            al[i][0] = Alo[(rb + g) * 68 + kw + t];
            al[i][1] = Alo[(rb + g + 8) * 68 + kw + t];
            al[i][2] = Alo[(rb + g) * 68 + kw + t + 4];
            al[i][3] = Alo[(rb + g + 8) * 68 + kw + t + 4];
        }
        u32 zrow = smb + 69632 + (u32)(kc * 16 + krow_off) * 272;
        #pragma unroll
        for (int jp = 0; jp < 4; jp++) {
            u32 addr = zrow + (u32)(wn * 64 + jp * 16 + ncol_off) * 2;
            u32 bh[4], bl[4];
            asm volatile("ldmatrix.sync.aligned.m8n8.x4.trans.shared.b16 {%0,%1,%2,%3}, [%4];"
                : "=r"(bh[0]), "=r"(bh[1]), "=r"(bh[2]), "=r"(bh[3]) : "r"(addr));
            asm volatile("ldmatrix.sync.aligned.m8n8.x4.trans.shared.b16 {%0,%1,%2,%3}, [%4];"
                : "=r"(bl[0]), "=r"(bl[1]), "=r"(bl[2]), "=r"(bl[3]) : "r"(addr + 34816));
            #pragma unroll
            for (int i = 0; i < 2; i++) {
                mma16816(acc[i][2 * jp],     ah[i], bh);
                mma16816(acc[i][2 * jp + 1], ah[i], bh + 2);
                mma16816(acc[i][2 * jp],     al[i], bh);
                mma16816(acc[i][2 * jp + 1], al[i], bh + 2);
                mma16816(acc[i][2 * jp],     ah[i], bl);
                mma16816(acc[i][2 * jp + 1], ah[i], bl + 2);
            }
        }
    }

    // repack interm into the Z region as hi/lo [n][136]
    __syncthreads();
    #pragma unroll
    for (int i = 0; i < 2; i++) {
        int nr = wm * 32 + i * 16 + g;
        #pragma unroll
        for (int j = 0; j < 8; j++) {
            int col = wn * 64 + j * 8 + 2 * t;
            u32 h, l;
            pack_hilo(acc[i][j][0], acc[i][j][1], h, l);
            *(u32*)(sm + 69632 + (u32)nr * 272 + col * 2) = h;
            *(u32*)(sm + 104448 + (u32)nr * 272 + col * 2) = l;
            pack_hilo(acc[i][j][2], acc[i][j][3], h, l);
            *(u32*)(sm + 69632 + (u32)(nr + 8) * 272 + col * 2) = h;
            *(u32*)(sm + 104448 + (u32)(nr + 8) * 272 + col * 2) = l;
        }
    }
    __syncthreads();

    // phase 2: out = interm @ Wv^T + bv
    #pragma unroll
    for (int i = 0; i < 2; i++)
        #pragma unroll
        for (int j = 0; j < 8; j++)
            #pragma unroll
            for (int q = 0; q < 4; q++) acc[i][j][q] = 0.f;

    const u32* Ih = (const u32*)(sm + 69632);
    const u32* Il = (const u32*)(sm + 104448);
    const u32* Wh = (const u32*)(sm + 139264);
    const u32* Wl = (const u32*)(sm + 174080);
    gemm_prod<8, 68>(acc, Ih, Wh, wm, wn, g, t);
    gemm_prod<8, 68>(acc, Ih, Wl, wm, wn, g, t);
    gemm_prod<8, 68>(acc, Il, Wh, wm, wn, g, t);

    #pragma unroll
    for (int i = 0; i < 2; i++) {
        int n0 = wm * 32 + i * 16 + g;
        size_t r0 = (size_t)n0 * 1024 + s_blk;
        size_t r1 = (size_t)(n0 + 8) * 1024 + s_blk;
        #pragma unroll
        for (int j = 0; j < 8; j++) {
            int e0 = wn * 64 + j * 8 + 2 * t;
            float2 bp = *(const float2*)(g_bv + e0);
            *(float2*)(out + r0 * 128 + e0) =
                make_float2(acc[i][j][0] + bp.x, acc[i][j][1] + bp.y);
            *(float2*)(out + r1 * 128 + e0) =
                make_float2(acc[i][j][2] + bp.x, acc[i][j][3] + bp.y);
        }
    }
}

// ---------------- launch ----------------
extern "C" void kernel_launch(void* const* d_in, const int* in_sizes, int n_in,
                              void* d_out, int out_size) {
    const float* x = nullptr; const float* W = nullptr; const float* b = nullptr;
    for (int i = 0; i < n_in; i++) {
        if      (in_sizes[i] == 16777216) x = (const float*)d_in[i];
        else if (in_sizes[i] == 49152)    W = (const float*)d_in[i];
        else if (in_sizes[i] == 384)      b = (const float*)d_in[i];
    }
    if (!x) x = (const float*)d_in[0];
    if (!W) W = (const float*)d_in[1];
    if (!b) b = (const float*)d_in[2];
    float* out = (float*)d_out;

    cudaFuncSetAttribute(k_yz, cudaFuncAttributeMaxDynamicSharedMemorySize, 108544);
    cudaFuncSetAttribute(k_sc, cudaFuncAttributeMaxDynamicSharedMemorySize, 147456);
    cudaFuncSetAttribute(k_xo, cudaFuncAttributeMaxDynamicSharedMemorySize, 208896);

    k_init_pe<<<1, 1024>>>();
    k_prep<<<128, 128>>>(W, b);
    k_prepA<<<128, 128>>>(W);
    k_yz<<<2048, 256, 108544>>>(x);
    k_csum<<<64, 256>>>();
    k_ab<<<1, 128>>>(b);
    k_sc<<<256, 256, 147456>>>();
    k_reduce<<<16, 256>>>();
    k_softmax<<<128, 128>>>();
    k_xo<<<1024, 256, 208896>>>(out);
}